// round 10
// baseline (speedup 1.0000x reference)
#include <cuda_runtime.h>

#define NN 50000
#define MM 800000
#define HH 64
#define EE 8
#define INN 16
#define DIN 137  // 1 + 2*H + E
#define LL 2

typedef unsigned long long u64;
typedef unsigned int u32;

// ---------------- device scratch (no allocs allowed) ----------------
__device__ float g_h0[NN * HH];
__device__ float g_h1[NN * HH];
__device__ float g_x[NN * 3];
__device__ float g_aggmsg[NN * HH];
__device__ float g_aggf[NN * 4];
__device__ int   g_degi[NN];
__device__ int   g_start[NN];
__device__ int   g_cur[NN];
__device__ int   g_srow[MM];
__device__ int   g_scol[MM];
__device__ float g_sef[MM * EE];
__device__ float g_A[NN * HH];     // h @ W1[1:65] + b1
__device__ float g_B[NN * HH];     // h @ W1[65:129]

__device__ __forceinline__ float silu_f(float v) {
    return __fdividef(v, 1.0f + __expf(-v));
}
__device__ __forceinline__ u64 pack2(float s) {
    u64 r; asm("mov.b64 %0, {%1, %1};" : "=l"(r) : "f"(s)); return r;
}
__device__ __forceinline__ void unpack2(u64 v, float& lo, float& hi) {
    asm("mov.b64 {%0, %1}, %2;" : "=f"(lo), "=f"(hi) : "l"(v));
}
__device__ __forceinline__ void fma2(u64& acc, u64 w, u64 s) {
    asm("fma.rn.f32x2 %0, %1, %2, %0;" : "+l"(acc) : "l"(w), "l"(s));
}
__device__ __forceinline__ void add2(u64& acc, u64 v) {
    asm("add.rn.f32x2 %0, %1, %0;" : "+l"(acc) : "l"(v));
}
__device__ __forceinline__ void red4(float* p, float a, float b, float c, float d) {
    asm volatile("red.global.add.v4.f32 [%0], {%1, %2, %3, %4};"
                 :: "l"(p), "f"(a), "f"(b), "f"(c), "f"(d) : "memory");
}
__host__ __device__ __forceinline__ int PERM(int j) {
    return (((j & 31) >> 2) << 3) + ((j >> 5) << 2) + (j & 3);
}
__host__ __device__ __forceinline__ int PERM4(int j) {
    return (((j & 15) >> 2) << 4) + ((j >> 4) << 2) + (j & 3);
}

// ---- pair helpers (k_node)
__device__ __forceinline__ void fmaPair(u64* a0, u64* a1, u64 s0, u64 s1,
                                        const float* wh) {
#pragma unroll
    for (int c = 0; c < 8; c++) {
        ulonglong2 t = *reinterpret_cast<const ulonglong2*>(wh + (c << 3));
        fma2(a0[2 * c],     t.x, s0);
        fma2(a0[2 * c + 1], t.y, s0);
        fma2(a1[2 * c],     t.x, s1);
        fma2(a1[2 * c + 1], t.y, s1);
    }
}
__device__ __forceinline__ void loadHalf(u64* a, const float* b, int h) {
    const ulonglong2* p = reinterpret_cast<const ulonglong2*>(b + (h << 5));
#pragma unroll
    for (int c = 0; c < 8; c++) {
        ulonglong2 v = p[c];
        a[2 * c] = v.x; a[2 * c + 1] = v.y;
    }
}
__device__ __forceinline__ void siluHalf(const u64* a, float* f) {
#pragma unroll
    for (int q = 0; q < 16; q++) {
        float x, y; unpack2(a[q], x, y);
        f[2 * q] = silu_f(x); f[2 * q + 1] = silu_f(y);
    }
}
// ---- quad helpers (edge)
__device__ __forceinline__ void fmaQuad(u64* a0, u64* a1, u64* a2, u64* a3,
                                        u64 s0, u64 s1, u64 s2, u64 s3,
                                        const float* wh) {
#pragma unroll
    for (int c = 0; c < 4; c++) {
        ulonglong2 t = *reinterpret_cast<const ulonglong2*>(wh + (c << 4));
        fma2(a0[2 * c], t.x, s0); fma2(a0[2 * c + 1], t.y, s0);
        fma2(a1[2 * c], t.x, s1); fma2(a1[2 * c + 1], t.y, s1);
        fma2(a2[2 * c], t.x, s2); fma2(a2[2 * c + 1], t.y, s2);
        fma2(a3[2 * c], t.x, s3); fma2(a3[2 * c + 1], t.y, s3);
    }
}
__device__ __forceinline__ void loadQuarter(u64* a, const float* b, int h) {
    const ulonglong2* p = reinterpret_cast<const ulonglong2*>(b + (h << 4));
#pragma unroll
    for (int c = 0; c < 4; c++) {
        ulonglong2 v = p[c];
        a[2 * c] = v.x; a[2 * c + 1] = v.y;
    }
}
__device__ __forceinline__ void siluQuarter(const u64* a, float* f) {
#pragma unroll
    for (int m = 0; m < 8; m++) {
        float x, y; unpack2(a[m], x, y);
        f[2 * m] = silu_f(x); f[2 * m + 1] = silu_f(y);
    }
}
// load A[r] quarter into av
__device__ __forceinline__ void loadA(u64* av, int r, int h) {
    const ulonglong2* pa = (const ulonglong2*)(g_A + (size_t)r * HH + (h << 4));
#pragma unroll
    for (int q = 0; q < 4; q++) {
        ulonglong2 v = pa[q];
        av[2 * q] = v.x; av[2 * q + 1] = v.y;
    }
}
// a = av + B[c] quarter
__device__ __forceinline__ void initFromAB(u64* a, const u64* av, int c, int h) {
    const ulonglong2* pb = (const ulonglong2*)(g_B + (size_t)c * HH + (h << 4));
#pragma unroll
    for (int q = 0; q < 4; q++) {
        ulonglong2 vb = pb[q];
        u64 x = av[2 * q];     add2(x, vb.x); a[2 * q] = x;
        u64 y = av[2 * q + 1]; add2(y, vb.y); a[2 * q + 1] = y;
    }
}
// ---- broadcast helpers
__device__ __forceinline__ void fmaB(u64* acc, u64 s2, const float* w) {
    const ulonglong2* w2 = reinterpret_cast<const ulonglong2*>(w);
#pragma unroll
    for (int q = 0; q < 16; q++) {
        ulonglong2 t = w2[q];
        fma2(acc[2 * q], t.x, s2); fma2(acc[2 * q + 1], t.y, s2);
    }
}
__device__ __forceinline__ void loadB(u64* acc, const float* b) {
    const ulonglong2* p = reinterpret_cast<const ulonglong2*>(b);
#pragma unroll
    for (int q = 0; q < 16; q++) {
        ulonglong2 v = p[q];
        acc[2 * q] = v.x; acc[2 * q + 1] = v.y;
    }
}
__device__ __forceinline__ void storeB(float* dst, const u64* acc) {
    ulonglong2* p = (ulonglong2*)dst;
#pragma unroll
    for (int q = 0; q < 16; q++)
        p[q] = make_ulonglong2(acc[2 * q], acc[2 * q + 1]);
}

// ---------------- sort infrastructure ----------------
__global__ void k_hist(const int* __restrict__ row) {
    int e = blockIdx.x * blockDim.x + threadIdx.x;
    if (e < MM) atomicAdd(&g_degi[row[e]], 1);
}

// single block, 512 threads; chunked exclusive scan of g_degi -> g_start
__global__ __launch_bounds__(512) void k_scan() {
    __shared__ int part[512];
    const int t = threadIdx.x;
    const int CH = (NN + 511) / 512;   // 98
    const int base = t * CH;
    int s = 0;
    for (int i = 0; i < CH; i++) {
        int n = base + i;
        if (n < NN) s += g_degi[n];
    }
    part[t] = s;
    __syncthreads();
    for (int off = 1; off < 512; off <<= 1) {
        int v = (t >= off) ? part[t - off] : 0;
        __syncthreads();
        part[t] += v;
        __syncthreads();
    }
    int run = (t == 0) ? 0 : part[t - 1];
    for (int i = 0; i < CH; i++) {
        int n = base + i;
        if (n < NN) {
            g_start[n] = run;
            run += g_degi[n];
        }
    }
}

__global__ void k_scatter(const int* __restrict__ row, const int* __restrict__ col,
                          const float* __restrict__ efea) {
    int e = blockIdx.x * blockDim.x + threadIdx.x;
    if (e >= MM) return;
    int r = row[e];
    int pos = g_start[r] + atomicAdd(&g_cur[r], 1);
    g_srow[pos] = r;
    g_scol[pos] = col[e];
    const float4* src = (const float4*)(efea + (size_t)e * EE);
    float4* dst = (float4*)(g_sef + (size_t)pos * EE);
    dst[0] = src[0];
    dst[1] = src[1];
}

// ---------------- embedding ----------------
__global__ __launch_bounds__(128) void k_embed(const float* __restrict__ h_in,
                                               const float* __restrict__ W,
                                               const float* __restrict__ b) {
    __shared__ float sW[INN * HH];
    __shared__ float sb[HH];
    for (int i = threadIdx.x; i < INN * HH; i += blockDim.x) sW[i] = W[i];
    for (int i = threadIdx.x; i < HH; i += blockDim.x) sb[i] = b[i];
    __syncthreads();
    int n = blockIdx.x * blockDim.x + threadIdx.x;
    if (n >= NN) return;
    u64 acc[32];
    loadB(acc, sb);
    const float4* hv = (const float4*)(h_in + (size_t)n * INN);
#pragma unroll
    for (int q = 0; q < INN / 4; q++) {
        float4 v = hv[q];
        fmaB(acc, pack2(v.x), sW + (4 * q + 0) * HH);
        fmaB(acc, pack2(v.y), sW + (4 * q + 1) * HH);
        fmaB(acc, pack2(v.z), sW + (4 * q + 2) * HH);
        fmaB(acc, pack2(v.w), sW + (4 * q + 3) * HH);
    }
    storeB(g_h0 + (size_t)n * HH, acc);
}

// ---------------- per-node precompute ----------------
#define PRE_SMEM_FLOATS (2 * HH * HH + HH)
__global__ __launch_bounds__(128) void k_pre(const float* __restrict__ h_in,
                                             const float* __restrict__ W1,
                                             const float* __restrict__ B1) {
    extern __shared__ float sm[];
    float* sWa = sm;
    float* sWb = sWa + HH * HH;
    float* sb  = sWb + HH * HH;
    const int t = threadIdx.x;
    for (int i = t; i < HH * HH; i += 128) {
        sWa[i] = W1[(1 + (i >> 6)) * HH + (i & 63)];
        sWb[i] = W1[(1 + HH + (i >> 6)) * HH + (i & 63)];
    }
    for (int i = t; i < HH; i += 128) sb[i] = B1[i];
    __syncthreads();
    int n = blockIdx.x * 128 + t;
    if (n >= NN) return;
    float hv[HH];
    {
        const float4* p = (const float4*)(h_in + (size_t)n * HH);
#pragma unroll
        for (int q = 0; q < 16; q++) {
            float4 v = p[q];
            hv[4 * q] = v.x; hv[4 * q + 1] = v.y;
            hv[4 * q + 2] = v.z; hv[4 * q + 3] = v.w;
        }
    }
    u64 acc[32];
    loadB(acc, sb);
#pragma unroll
    for (int k = 0; k < HH; k++) fmaB(acc, pack2(hv[k]), sWa + k * HH);
    storeB(g_A + (size_t)n * HH, acc);
#pragma unroll
    for (int q = 0; q < 32; q++) acc[q] = 0ull;
#pragma unroll
    for (int k = 0; k < HH; k++) fmaB(acc, pack2(hv[k]), sWb + k * HH);
    storeB(g_B + (size_t)n * HH, acc);
}

// ===== edge kernel: 256 thr, quad-split, sorted edges, fast paths =========
#define EDGE_SMEM_FLOATS (9 * HH + 2 * HH * HH + 3 * HH + 4 + 8 * HH * 32)

__global__ __launch_bounds__(256, 2) void k_edge(
    const float* __restrict__ W1,
    const float* __restrict__ W2, const float* __restrict__ B2,
    const float* __restrict__ CW1, const float* __restrict__ CB1,
    const float* __restrict__ CW2, const float* __restrict__ CB2) {
    extern __shared__ float sm[];
    float* sW1e = sm;                  // [9][64] PERM4
    float* sW2p = sW1e + 9 * HH;       // [64][64] PERM4
    float* sCW1 = sW2p + HH * HH;      // [64][64] PERM4
    float* sB2  = sCW1 + HH * HH;
    float* sCB1 = sB2 + HH;
    float* sCW2 = sCB1 + HH;
    float* sCB2 = sCW2 + HH;
    float* sStg = sCB2 + 4;            // 8 * 2048

    const int t = threadIdx.x;
    for (int i = t; i < 9 * HH; i += 256) {
        int k = i >> 6, j = i & 63;
        int srcRow = (k == 0) ? 0 : (1 + 2 * HH + (k - 1));
        sW1e[(k << 6) + PERM4(j)] = W1[srcRow * HH + j];
    }
    for (int i = t; i < HH * HH; i += 256) {
        int k = i >> 6, j = i & 63;
        int p = (k << 6) + PERM4(j);
        sW2p[p] = W2[i];
        sCW1[p] = CW1[i];
    }
    for (int i = t; i < HH; i += 256) {
        sB2[i] = B2[i]; sCB1[i] = CB1[i]; sCW2[i] = CW2[i];
    }
    if (t == 0) sCB2[0] = CB2[0];
    __syncthreads();

    const int wid = t >> 5, lane = t & 31;
    const int h = lane & 3, qd = lane >> 2, h4 = h << 2;
    float4* stW = (float4*)(sStg + wid * (HH * 32));  // [64 rows][8 float4]

    const int e0 = blockIdx.x * 256 + (wid << 5) + (qd << 2);
    const int4 rv = *(const int4*)(g_srow + e0);
    const int4 cv = *(const int4*)(g_scol + e0);
    const int r0 = rv.x, r1 = rv.y, r2i = rv.z, r3 = rv.w;
    const int c0 = cv.x, c1 = cv.y, c2 = cv.z, c3 = cv.w;
    const bool same = (r0 == r3);   // sorted => all four equal

    const float xr0 = g_x[r0 * 3 + 0], xr0y = g_x[r0 * 3 + 1], xr0z = g_x[r0 * 3 + 2];
    float rx0, ry0, rz0, rx1, ry1, rz1, rx2, ry2, rz2, rx3, ry3, rz3;
    rx0 = xr0 - g_x[c0 * 3 + 0]; ry0 = xr0y - g_x[c0 * 3 + 1]; rz0 = xr0z - g_x[c0 * 3 + 2];
    if (same) {
        rx1 = xr0 - g_x[c1 * 3 + 0]; ry1 = xr0y - g_x[c1 * 3 + 1]; rz1 = xr0z - g_x[c1 * 3 + 2];
        rx2 = xr0 - g_x[c2 * 3 + 0]; ry2 = xr0y - g_x[c2 * 3 + 1]; rz2 = xr0z - g_x[c2 * 3 + 2];
        rx3 = xr0 - g_x[c3 * 3 + 0]; ry3 = xr0y - g_x[c3 * 3 + 1]; rz3 = xr0z - g_x[c3 * 3 + 2];
    } else {
        rx1 = g_x[r1 * 3 + 0] - g_x[c1 * 3 + 0];
        ry1 = g_x[r1 * 3 + 1] - g_x[c1 * 3 + 1];
        rz1 = g_x[r1 * 3 + 2] - g_x[c1 * 3 + 2];
        rx2 = g_x[r2i * 3 + 0] - g_x[c2 * 3 + 0];
        ry2 = g_x[r2i * 3 + 1] - g_x[c2 * 3 + 1];
        rz2 = g_x[r2i * 3 + 2] - g_x[c2 * 3 + 2];
        rx3 = g_x[r3 * 3 + 0] - g_x[c3 * 3 + 0];
        ry3 = g_x[r3 * 3 + 1] - g_x[c3 * 3 + 1];
        rz3 = g_x[r3 * 3 + 2] - g_x[c3 * 3 + 2];
    }
    const float s2_0 = rx0 * rx0 + ry0 * ry0 + rz0 * rz0;
    const float s2_1 = rx1 * rx1 + ry1 * ry1 + rz1 * rz1;
    const float s2_2 = rx2 * rx2 + ry2 * ry2 + rz2 * rz2;
    const float s2_3 = rx3 * rx3 + ry3 * ry3 + rz3 * rz3;

    float sx, sy, sz;
    if (h == 0)      { sx = rx0; sy = ry0; sz = rz0; }
    else if (h == 1) { sx = rx1; sy = ry1; sz = rz1; }
    else if (h == 2) { sx = rx2; sy = ry2; sz = rz2; }
    else             { sx = rx3; sy = ry3; sz = rz3; }

    u64 a0[8], a1[8], a2[8], a3[8];

    // ---- stage 1 (factored): acc = A[r]+B[c] + r2*w0 + ef@Wef ----
    {
        u64 av[8];
        loadA(av, r0, h);
        initFromAB(a0, av, c0, h);
        if (same) {
            initFromAB(a1, av, c1, h);
            initFromAB(a2, av, c2, h);
            initFromAB(a3, av, c3, h);
        } else {
            u64 av1[8], av2[8], av3[8];
            loadA(av1, r1, h);
            loadA(av2, r2i, h);
            loadA(av3, r3, h);
            initFromAB(a1, av1, c1, h);
            initFromAB(a2, av2, c2, h);
            initFromAB(a3, av3, c3, h);
        }
    }
    fmaQuad(a0, a1, a2, a3, pack2(s2_0), pack2(s2_1), pack2(s2_2), pack2(s2_3),
            sW1e + h4);
    {
        const float4* ef0 = (const float4*)(g_sef + (size_t)e0 * EE);
        const float4* ef1 = (const float4*)(g_sef + (size_t)(e0 + 1) * EE);
        const float4* ef2 = (const float4*)(g_sef + (size_t)(e0 + 2) * EE);
        const float4* ef3 = (const float4*)(g_sef + (size_t)(e0 + 3) * EE);
#pragma unroll
        for (int q = 0; q < 2; q++) {
            float4 u0 = ef0[q], u1 = ef1[q], u2 = ef2[q], u3 = ef3[q];
            fmaQuad(a0, a1, a2, a3, pack2(u0.x), pack2(u1.x), pack2(u2.x), pack2(u3.x),
                    sW1e + ((1 + 4 * q + 0) << 6) + h4);
            fmaQuad(a0, a1, a2, a3, pack2(u0.y), pack2(u1.y), pack2(u2.y), pack2(u3.y),
                    sW1e + ((1 + 4 * q + 1) << 6) + h4);
            fmaQuad(a0, a1, a2, a3, pack2(u0.z), pack2(u1.z), pack2(u2.z), pack2(u3.z),
                    sW1e + ((1 + 4 * q + 2) << 6) + h4);
            fmaQuad(a0, a1, a2, a3, pack2(u0.w), pack2(u1.w), pack2(u2.w), pack2(u3.w),
                    sW1e + ((1 + 4 * q + 3) << 6) + h4);
        }
    }
    {
        float f0[16], f1[16], f2[16], f3[16];
        siluQuarter(a0, f0);
        siluQuarter(a1, f1);
        siluQuarter(a2, f2);
        siluQuarter(a3, f3);
#pragma unroll
        for (int m = 0; m < 16; m++)
            stW[((h << 4) + m) * 8 + qd] = make_float4(f0[m], f1[m], f2[m], f3[m]);
    }
    __syncwarp();

    // ---- stage 2: msg = silu(hid @ W2 + b2) ----
    loadQuarter(a0, sB2, h);
#pragma unroll
    for (int m = 0; m < 8; m++) { a1[m] = a0[m]; a2[m] = a0[m]; a3[m] = a0[m]; }
#pragma unroll
    for (int k = 0; k < HH; k++) {
        float4 s = stW[k * 8 + qd];
        fmaQuad(a0, a1, a2, a3, pack2(s.x), pack2(s.y), pack2(s.z), pack2(s.w),
                sW2p + (k << 6) + h4);
    }
    __syncwarp();
    {
        float m0[16], m1[16], m2[16], m3[16];
        siluQuarter(a0, m0);
        siluQuarter(a1, m1);
        siluQuarter(a2, m2);
        siluQuarter(a3, m3);
        const int jo = h << 4;
        if (same) {
            float* am = &g_aggmsg[(size_t)r0 * HH + jo];
#pragma unroll
            for (int i = 0; i < 16; i++) m0[i] += m1[i] + m2[i] + m3[i];
#pragma unroll
            for (int c = 0; c < 4; c++)
                red4(am + 4 * c, m0[4 * c], m0[4 * c + 1], m0[4 * c + 2], m0[4 * c + 3]);
        } else {
            float* am0 = &g_aggmsg[(size_t)r0 * HH + jo];
            float* am1 = &g_aggmsg[(size_t)r1 * HH + jo];
            float* am2 = &g_aggmsg[(size_t)r2i * HH + jo];
            float* am3 = &g_aggmsg[(size_t)r3 * HH + jo];
#pragma unroll
            for (int c = 0; c < 4; c++) {
                red4(am0 + 4 * c, m0[4 * c], m0[4 * c + 1], m0[4 * c + 2], m0[4 * c + 3]);
                red4(am1 + 4 * c, m1[4 * c], m1[4 * c + 1], m1[4 * c + 2], m1[4 * c + 3]);
                red4(am2 + 4 * c, m2[4 * c], m2[4 * c + 1], m2[4 * c + 2], m2[4 * c + 3]);
                red4(am3 + 4 * c, m3[4 * c], m3[4 * c + 1], m3[4 * c + 2], m3[4 * c + 3]);
            }
        }
        // re-stage msg for stage 3
#pragma unroll
        for (int m = 0; m < 16; m++)
            stW[((h << 4) + m) * 8 + qd] = make_float4(m0[m], m1[m], m2[m], m3[m]);
        // note: when same==true, m0 now holds the SUM -- must not be used for
        // stage-3 staging!  Undo: stage-3 needs per-edge msg.  Re-derive:
        if (same) {
#pragma unroll
            for (int m = 0; m < 16; m++) {
                float orig0 = m0[m] - m1[m] - m2[m] - m3[m];
                stW[((h << 4) + m) * 8 + qd] = make_float4(orig0, m1[m], m2[m], m3[m]);
            }
        }
    }
    __syncwarp();

    // ---- stage 3: cm = silu(msg @ CW1 + cb1) . CW2 + cb2 ----
    loadQuarter(a0, sCB1, h);
#pragma unroll
    for (int m = 0; m < 8; m++) { a1[m] = a0[m]; a2[m] = a0[m]; a3[m] = a0[m]; }
#pragma unroll
    for (int k = 0; k < HH; k++) {
        float4 s = stW[k * 8 + qd];
        fmaQuad(a0, a1, a2, a3, pack2(s.x), pack2(s.y), pack2(s.z), pack2(s.w),
                sCW1 + (k << 6) + h4);
    }
    float cm0 = 0.0f, cm1 = 0.0f, cm2 = 0.0f, cm3 = 0.0f;
#pragma unroll
    for (int m = 0; m < 8; m++) {
        const int j = (h << 4) + 2 * m;
        const float wA = sCW2[j], wB = sCW2[j + 1];
        float x, y;
        unpack2(a0[m], x, y); cm0 += silu_f(x) * wA + silu_f(y) * wB;
        unpack2(a1[m], x, y); cm1 += silu_f(x) * wA + silu_f(y) * wB;
        unpack2(a2[m], x, y); cm2 += silu_f(x) * wA + silu_f(y) * wB;
        unpack2(a3[m], x, y); cm3 += silu_f(x) * wA + silu_f(y) * wB;
    }
    cm0 += __shfl_xor_sync(0xffffffffu, cm0, 1);
    cm0 += __shfl_xor_sync(0xffffffffu, cm0, 2);
    cm1 += __shfl_xor_sync(0xffffffffu, cm1, 1);
    cm1 += __shfl_xor_sync(0xffffffffu, cm1, 2);
    cm2 += __shfl_xor_sync(0xffffffffu, cm2, 1);
    cm2 += __shfl_xor_sync(0xffffffffu, cm2, 2);
    cm3 += __shfl_xor_sync(0xffffffffu, cm3, 1);
    cm3 += __shfl_xor_sync(0xffffffffu, cm3, 2);
    const float cb2v = sCB2[0];
    float cm; int re;
    if (h == 0)      { cm = cm0 + cb2v; re = r0; }
    else if (h == 1) { cm = cm1 + cb2v; re = r1; }
    else if (h == 2) { cm = cm2 + cb2v; re = r2i; }
    else             { cm = cm3 + cb2v; re = r3; }
    float fx = sx * cm, fy = sy * cm, fz = sz * cm;
    // same is quad-uniform: all 4 lanes of the quad take the same branch
    if (same) {
        const u32 qmask = 0xFu << (lane & ~3);
        fx += __shfl_xor_sync(qmask, fx, 1);
        fy += __shfl_xor_sync(qmask, fy, 1);
        fz += __shfl_xor_sync(qmask, fz, 1);
        fx += __shfl_xor_sync(qmask, fx, 2);
        fy += __shfl_xor_sync(qmask, fy, 2);
        fz += __shfl_xor_sync(qmask, fz, 2);
        if (h == 0) red4(&g_aggf[(size_t)r0 * 4], fx, fy, fz, 0.0f);
    } else {
        red4(&g_aggf[(size_t)re * 4], fx, fy, fz, 0.0f);
    }
}

// ---------------- node kernel (pair-split) ----------------
#define NODE_SMEM_FLOATS (2 * HH * HH + HH * HH + 2 * HH)
__global__ __launch_bounds__(128, 3) void k_node(
    const float* __restrict__ h_in, float* __restrict__ h_out,
    const float* __restrict__ NW1, const float* __restrict__ NB1,
    const float* __restrict__ NW2, const float* __restrict__ NB2,
    float* __restrict__ out_x, float* __restrict__ out_h, int writeOut) {
    extern __shared__ float sm[];
    float* sW1 = sm;
    float* sW2 = sW1 + 2 * HH * HH;
    float* sB1 = sW2 + HH * HH;
    float* sB2 = sB1 + HH;
    const int t = threadIdx.x;
    for (int i = t; i < 2 * HH * HH; i += 128) {
        int k = i >> 6, j = i & 63;
        sW1[(k << 6) + PERM(j)] = NW1[i];
    }
    for (int i = t; i < HH * HH; i += 128) {
        int k = i >> 6, j = i & 63;
        sW2[(k << 6) + PERM(j)] = NW2[i];
    }
    for (int i = t; i < HH; i += 128) { sB1[i] = NB1[i]; sB2[i] = NB2[i]; }
    __syncthreads();

    const int lane = t & 31;
    const int h = lane & 1;
    int n0 = (blockIdx.x * 64 + ((t >> 5) << 4) + (lane >> 1)) * 2;
    const bool valid = (n0 < NN);
    if (!valid) n0 = NN - 2;
    const int n1 = n0 + 1;
    const int h4 = h << 2;

    u64 a0[16], a1[16];
    loadHalf(a0, sB1, h);
#pragma unroll
    for (int m = 0; m < 16; m++) a1[m] = a0[m];
    {
        const float4* p0 = (const float4*)(h_in + (size_t)n0 * HH);
        const float4* p1 = (const float4*)(h_in + (size_t)n1 * HH);
#pragma unroll
        for (int q = 0; q < 16; q++) {
            float4 u = p0[q], v = p1[q];
            fmaPair(a0, a1, pack2(u.x), pack2(v.x), sW1 + ((4 * q + 0) << 6) + h4);
            fmaPair(a0, a1, pack2(u.y), pack2(v.y), sW1 + ((4 * q + 1) << 6) + h4);
            fmaPair(a0, a1, pack2(u.z), pack2(v.z), sW1 + ((4 * q + 2) << 6) + h4);
            fmaPair(a0, a1, pack2(u.w), pack2(v.w), sW1 + ((4 * q + 3) << 6) + h4);
        }
        const float4* m0 = (const float4*)(g_aggmsg + (size_t)n0 * HH);
        const float4* m1 = (const float4*)(g_aggmsg + (size_t)n1 * HH);
#pragma unroll
        for (int q = 0; q < 16; q++) {
            float4 u = m0[q], v = m1[q];
            fmaPair(a0, a1, pack2(u.x), pack2(v.x), sW1 + ((HH + 4 * q + 0) << 6) + h4);
            fmaPair(a0, a1, pack2(u.y), pack2(v.y), sW1 + ((HH + 4 * q + 1) << 6) + h4);
            fmaPair(a0, a1, pack2(u.z), pack2(v.z), sW1 + ((HH + 4 * q + 2) << 6) + h4);
            fmaPair(a0, a1, pack2(u.w), pack2(v.w), sW1 + ((HH + 4 * q + 3) << 6) + h4);
        }
    }
    float hid0[32], hid1[32];
    siluHalf(a0, hid0);
    siluHalf(a1, hid1);

    loadHalf(a0, sB2, h);
#pragma unroll
    for (int m = 0; m < 16; m++) a1[m] = a0[m];
#pragma unroll
    for (int k = 0; k < HH; k++) {
        const int src = (lane & ~1) | (k >> 5);
        float s0 = __shfl_sync(0xffffffffu, hid0[k & 31], src);
        float s1 = __shfl_sync(0xffffffffu, hid1[k & 31], src);
        fmaPair(a0, a1, pack2(s0), pack2(s1), sW2 + (k << 6) + h4);
    }

    if (valid) {
        const int jo = h << 5;
        ulonglong2* o0 = (ulonglong2*)(h_out + (size_t)n0 * HH + jo);
        ulonglong2* o1 = (ulonglong2*)(h_out + (size_t)n1 * HH + jo);
#pragma unroll
        for (int c = 0; c < 8; c++) {
            o0[c] = make_ulonglong2(a0[2 * c], a0[2 * c + 1]);
            o1[c] = make_ulonglong2(a1[2 * c], a1[2 * c + 1]);
        }
        if (writeOut) {
            ulonglong2* q0 = (ulonglong2*)(out_h + (size_t)n0 * HH + jo);
            ulonglong2* q1 = (ulonglong2*)(out_h + (size_t)n1 * HH + jo);
#pragma unroll
            for (int c = 0; c < 8; c++) {
                q0[c] = make_ulonglong2(a0[2 * c], a0[2 * c + 1]);
                q1[c] = make_ulonglong2(a1[2 * c], a1[2 * c + 1]);
            }
        }
        const int n = n0 + h;
        float cnt = (float)g_degi[n];
        float inv = 1.0f / fmaxf(cnt, 1.0f);
#pragma unroll
        for (int d = 0; d < 3; d++) {
            float tot = g_aggf[(size_t)n * 4 + d] * inv;
            tot = fminf(fmaxf(tot, -100.0f), 100.0f);
            float nx = g_x[n * 3 + d] + tot;
            g_x[n * 3 + d] = nx;
            if (writeOut) out_x[n * 3 + d] = nx;
        }
    }
}

// ---------------- launch ----------------
extern "C" void kernel_launch(void* const* d_in, const int* in_sizes, int n_in,
                              void* d_out, int out_size) {
    const float* x    = (const float*)d_in[0];
    const float* h    = (const float*)d_in[1];
    const int*   row  = (const int*)d_in[2];
    const int*   col  = (const int*)d_in[3];
    const float* efea = (const float*)d_in[4];
    const float* embW = (const float*)d_in[5];
    const float* embB = (const float*)d_in[6];
    const float* eW1  = (const float*)d_in[7];
    const float* eB1  = (const float*)d_in[8];
    const float* eW2  = (const float*)d_in[9];
    const float* eB2  = (const float*)d_in[10];
    const float* cW1  = (const float*)d_in[11];
    const float* cB1  = (const float*)d_in[12];
    const float* cW2  = (const float*)d_in[13];
    const float* cB2  = (const float*)d_in[14];
    const float* nW1  = (const float*)d_in[15];
    const float* nB1  = (const float*)d_in[16];
    const float* nW2  = (const float*)d_in[17];
    const float* nB2  = (const float*)d_in[18];
    float* out = (float*)d_out;

    void *p_x, *p_h0, *p_h1, *p_am, *p_af, *p_deg, *p_cur;
    cudaGetSymbolAddress(&p_x, g_x);
    cudaGetSymbolAddress(&p_h0, g_h0);
    cudaGetSymbolAddress(&p_h1, g_h1);
    cudaGetSymbolAddress(&p_am, g_aggmsg);
    cudaGetSymbolAddress(&p_af, g_aggf);
    cudaGetSymbolAddress(&p_deg, g_degi);
    cudaGetSymbolAddress(&p_cur, g_cur);

    const int edge_smem = EDGE_SMEM_FLOATS * sizeof(float);
    const int node_smem = NODE_SMEM_FLOATS * sizeof(float);
    const int pre_smem  = PRE_SMEM_FLOATS * sizeof(float);
    cudaFuncSetAttribute(k_edge, cudaFuncAttributeMaxDynamicSharedMemorySize, edge_smem);
    cudaFuncSetAttribute(k_node, cudaFuncAttributeMaxDynamicSharedMemorySize, node_smem);
    cudaFuncSetAttribute(k_pre,  cudaFuncAttributeMaxDynamicSharedMemorySize, pre_smem);

    cudaMemcpyAsync(p_x, x, NN * 3 * sizeof(float), cudaMemcpyDeviceToDevice, 0);
    cudaMemsetAsync(p_deg, 0, NN * sizeof(int), 0);
    cudaMemsetAsync(p_cur, 0, NN * sizeof(int), 0);
    k_hist<<<(MM + 255) / 256, 256>>>(row);
    k_scan<<<1, 512>>>();
    k_scatter<<<(MM + 255) / 256, 256>>>(row, col, efea);
    k_embed<<<(NN + 127) / 128, 128>>>(h, embW, embB);

    float* hbuf[2] = {(float*)p_h0, (float*)p_h1};
    float* out_x = out;
    float* out_h = out + (size_t)NN * 3;
    const int node_grid = (NN / 2 + 63) / 64;   // 391

    for (int i = 0; i < LL; i++) {
        cudaMemsetAsync(p_am, 0, (size_t)NN * HH * sizeof(float), 0);
        cudaMemsetAsync(p_af, 0, (size_t)NN * 4 * sizeof(float), 0);
        k_pre<<<(NN + 127) / 128, 128, pre_smem>>>(
            hbuf[i & 1], eW1 + (size_t)i * DIN * HH, eB1 + (size_t)i * HH);
        k_edge<<<MM / 256, 256, edge_smem>>>(
            eW1 + (size_t)i * DIN * HH,
            eW2 + (size_t)i * HH * HH,  eB2 + (size_t)i * HH,
            cW1 + (size_t)i * HH * HH,  cB1 + (size_t)i * HH,
            cW2 + (size_t)i * HH,       cB2 + (size_t)i * 1);
        k_node<<<node_grid, 128, node_smem>>>(
            hbuf[i & 1], hbuf[(i + 1) & 1],
            nW1 + (size_t)i * 2 * HH * HH, nB1 + (size_t)i * HH,
            nW2 + (size_t)i * HH * HH,     nB2 + (size_t)i * HH,
            out_x, out_h, (i == LL - 1) ? 1 : 0);
    }
    (void)in_sizes; (void)n_in; (void)out_size;
}

// round 11
// speedup vs baseline: 1.0081x; 1.0081x over previous
#include <cuda_runtime.h>

#define NN 50000
#define MM 800000
#define HH 64
#define EE 8
#define INN 16
#define DIN 137  // 1 + 2*H + E
#define LL 2

typedef unsigned long long u64;
typedef unsigned int u32;

// ---------------- device scratch (no allocs allowed) ----------------
__device__ float g_h0[NN * HH];
__device__ float g_h1[NN * HH];
__device__ float g_x[NN * 3];
__device__ float g_aggmsg[NN * HH];
__device__ float g_aggf[NN * 4];
__device__ float g_cnt[NN];
__device__ float g_A[NN * HH];     // h @ W1[1:65] + b1
__device__ float g_B[NN * HH];     // h @ W1[65:129]

__device__ __forceinline__ float silu_f(float v) {
    return __fdividef(v, 1.0f + __expf(-v));
}
__device__ __forceinline__ u64 pack2(float s) {
    u64 r; asm("mov.b64 %0, {%1, %1};" : "=l"(r) : "f"(s)); return r;
}
__device__ __forceinline__ void unpack2(u64 v, float& lo, float& hi) {
    asm("mov.b64 {%0, %1}, %2;" : "=f"(lo), "=f"(hi) : "l"(v));
}
__device__ __forceinline__ void fma2(u64& acc, u64 w, u64 s) {
    asm("fma.rn.f32x2 %0, %1, %2, %0;" : "+l"(acc) : "l"(w), "l"(s));
}
__device__ __forceinline__ void add2(u64& acc, u64 v) {
    asm("add.rn.f32x2 %0, %1, %0;" : "+l"(acc) : "l"(v));
}
__device__ __forceinline__ void red4(float* p, float a, float b, float c, float d) {
    asm volatile("red.global.add.v4.f32 [%0], {%1, %2, %3, %4};"
                 :: "l"(p), "f"(a), "f"(b), "f"(c), "f"(d) : "memory");
}
__host__ __device__ __forceinline__ int PERM(int j) {
    return (((j & 31) >> 2) << 3) + ((j >> 5) << 2) + (j & 3);
}
__host__ __device__ __forceinline__ int PERM4(int j) {
    return (((j & 15) >> 2) << 4) + ((j >> 4) << 2) + (j & 3);
}

// ---- pair helpers (k_node)
__device__ __forceinline__ void fmaPair(u64* a0, u64* a1, u64 s0, u64 s1,
                                        const float* wh) {
#pragma unroll
    for (int c = 0; c < 8; c++) {
        ulonglong2 t = *reinterpret_cast<const ulonglong2*>(wh + (c << 3));
        fma2(a0[2 * c],     t.x, s0);
        fma2(a0[2 * c + 1], t.y, s0);
        fma2(a1[2 * c],     t.x, s1);
        fma2(a1[2 * c + 1], t.y, s1);
    }
}
__device__ __forceinline__ void loadHalf(u64* a, const float* b, int h) {
    const ulonglong2* p = reinterpret_cast<const ulonglong2*>(b + (h << 5));
#pragma unroll
    for (int c = 0; c < 8; c++) {
        ulonglong2 v = p[c];
        a[2 * c] = v.x; a[2 * c + 1] = v.y;
    }
}
__device__ __forceinline__ void siluHalf(const u64* a, float* f) {
#pragma unroll
    for (int q = 0; q < 16; q++) {
        float x, y; unpack2(a[q], x, y);
        f[2 * q] = silu_f(x); f[2 * q + 1] = silu_f(y);
    }
}
// ---- quad helpers (edge)
__device__ __forceinline__ void fmaQuad(u64* a0, u64* a1, u64* a2, u64* a3,
                                        u64 s0, u64 s1, u64 s2, u64 s3,
                                        const float* wh) {
#pragma unroll
    for (int c = 0; c < 4; c++) {
        ulonglong2 t = *reinterpret_cast<const ulonglong2*>(wh + (c << 4));
        fma2(a0[2 * c], t.x, s0); fma2(a0[2 * c + 1], t.y, s0);
        fma2(a1[2 * c], t.x, s1); fma2(a1[2 * c + 1], t.y, s1);
        fma2(a2[2 * c], t.x, s2); fma2(a2[2 * c + 1], t.y, s2);
        fma2(a3[2 * c], t.x, s3); fma2(a3[2 * c + 1], t.y, s3);
    }
}
__device__ __forceinline__ void loadQuarter(u64* a, const float* b, int h) {
    const ulonglong2* p = reinterpret_cast<const ulonglong2*>(b + (h << 4));
#pragma unroll
    for (int c = 0; c < 4; c++) {
        ulonglong2 v = p[c];
        a[2 * c] = v.x; a[2 * c + 1] = v.y;
    }
}
__device__ __forceinline__ void siluQuarter(const u64* a, float* f) {
#pragma unroll
    for (int m = 0; m < 8; m++) {
        float x, y; unpack2(a[m], x, y);
        f[2 * m] = silu_f(x); f[2 * m + 1] = silu_f(y);
    }
}
__device__ __forceinline__ void initAB(u64* a, int r, int c, int h) {
    const ulonglong2* pa = (const ulonglong2*)(g_A + (size_t)r * HH + (h << 4));
    const ulonglong2* pb = (const ulonglong2*)(g_B + (size_t)c * HH + (h << 4));
#pragma unroll
    for (int q = 0; q < 4; q++) {
        ulonglong2 va = pa[q], vb = pb[q];
        add2(va.x, vb.x); add2(va.y, vb.y);
        a[2 * q] = va.x; a[2 * q + 1] = va.y;
    }
}
// ---- broadcast helpers
__device__ __forceinline__ void fmaB(u64* acc, u64 s2, const float* w) {
    const ulonglong2* w2 = reinterpret_cast<const ulonglong2*>(w);
#pragma unroll
    for (int q = 0; q < 16; q++) {
        ulonglong2 t = w2[q];
        fma2(acc[2 * q], t.x, s2); fma2(acc[2 * q + 1], t.y, s2);
    }
}
__device__ __forceinline__ void loadB(u64* acc, const float* b) {
    const ulonglong2* p = reinterpret_cast<const ulonglong2*>(b);
#pragma unroll
    for (int q = 0; q < 16; q++) {
        ulonglong2 v = p[q];
        acc[2 * q] = v.x; acc[2 * q + 1] = v.y;
    }
}
__device__ __forceinline__ void storeB(float* dst, const u64* acc) {
    ulonglong2* p = (ulonglong2*)dst;
#pragma unroll
    for (int q = 0; q < 16; q++)
        p[q] = make_ulonglong2(acc[2 * q], acc[2 * q + 1]);
}

// ---------------- degree count ----------------
__global__ void k_cnt(const int* __restrict__ row) {
    int e = blockIdx.x * blockDim.x + threadIdx.x;
    if (e < MM) atomicAdd(&g_cnt[row[e]], 1.0f);
}

// -------- fused embedding + layer-0 A/B precompute --------
#define PREEMB_SMEM_FLOATS (INN * HH + 2 * HH * HH + 2 * HH)
__global__ __launch_bounds__(128) void k_embed_pre(
    const float* __restrict__ h_in,
    const float* __restrict__ embW, const float* __restrict__ embB,
    const float* __restrict__ W1, const float* __restrict__ B1) {
    extern __shared__ float sm[];
    float* sWe = sm;                  // [16][64]
    float* sWa = sWe + INN * HH;      // W1 rows 1..64
    float* sWb = sWa + HH * HH;       // W1 rows 65..128
    float* sbe = sWb + HH * HH;
    float* sb1 = sbe + HH;
    const int t = threadIdx.x;
    for (int i = t; i < INN * HH; i += 128) sWe[i] = embW[i];
    for (int i = t; i < HH * HH; i += 128) {
        sWa[i] = W1[(1 + (i >> 6)) * HH + (i & 63)];
        sWb[i] = W1[(1 + HH + (i >> 6)) * HH + (i & 63)];
    }
    for (int i = t; i < HH; i += 128) { sbe[i] = embB[i]; sb1[i] = B1[i]; }
    __syncthreads();
    int n = blockIdx.x * 128 + t;
    if (n >= NN) return;
    u64 acc[32];
    loadB(acc, sbe);
    const float4* hv4 = (const float4*)(h_in + (size_t)n * INN);
#pragma unroll
    for (int q = 0; q < INN / 4; q++) {
        float4 v = hv4[q];
        fmaB(acc, pack2(v.x), sWe + (4 * q + 0) * HH);
        fmaB(acc, pack2(v.y), sWe + (4 * q + 1) * HH);
        fmaB(acc, pack2(v.z), sWe + (4 * q + 2) * HH);
        fmaB(acc, pack2(v.w), sWe + (4 * q + 3) * HH);
    }
    storeB(g_h0 + (size_t)n * HH, acc);
    float hv[HH];
#pragma unroll
    for (int q = 0; q < 32; q++) unpack2(acc[q], hv[2 * q], hv[2 * q + 1]);
    loadB(acc, sb1);
#pragma unroll
    for (int k = 0; k < HH; k++) fmaB(acc, pack2(hv[k]), sWa + k * HH);
    storeB(g_A + (size_t)n * HH, acc);
#pragma unroll
    for (int q = 0; q < 32; q++) acc[q] = 0ull;
#pragma unroll
    for (int k = 0; k < HH; k++) fmaB(acc, pack2(hv[k]), sWb + k * HH);
    storeB(g_B + (size_t)n * HH, acc);
}

// ---------------- per-node precompute (layer >= 1) ----------------
#define PRE_SMEM_FLOATS (2 * HH * HH + HH)
__global__ __launch_bounds__(128) void k_pre(const float* __restrict__ h_in,
                                             const float* __restrict__ W1,
                                             const float* __restrict__ B1) {
    extern __shared__ float sm[];
    float* sWa = sm;
    float* sWb = sWa + HH * HH;
    float* sb  = sWb + HH * HH;
    const int t = threadIdx.x;
    for (int i = t; i < HH * HH; i += 128) {
        sWa[i] = W1[(1 + (i >> 6)) * HH + (i & 63)];
        sWb[i] = W1[(1 + HH + (i >> 6)) * HH + (i & 63)];
    }
    for (int i = t; i < HH; i += 128) sb[i] = B1[i];
    __syncthreads();
    int n = blockIdx.x * 128 + t;
    if (n >= NN) return;
    float hv[HH];
    {
        const float4* p = (const float4*)(h_in + (size_t)n * HH);
#pragma unroll
        for (int q = 0; q < 16; q++) {
            float4 v = p[q];
            hv[4 * q] = v.x; hv[4 * q + 1] = v.y;
            hv[4 * q + 2] = v.z; hv[4 * q + 3] = v.w;
        }
    }
    u64 acc[32];
    loadB(acc, sb);
#pragma unroll
    for (int k = 0; k < HH; k++) fmaB(acc, pack2(hv[k]), sWa + k * HH);
    storeB(g_A + (size_t)n * HH, acc);
#pragma unroll
    for (int q = 0; q < 32; q++) acc[q] = 0ull;
#pragma unroll
    for (int k = 0; k < HH; k++) fmaB(acc, pack2(hv[k]), sWb + k * HH);
    storeB(g_B + (size_t)n * HH, acc);
}

// ===== edge kernel: 256 thr, quad-split, smem-staged operands =============
#define EDGE_SMEM_FLOATS (9 * HH + 2 * HH * HH + 3 * HH + 4 + 8 * HH * 32)

__global__ __launch_bounds__(256, 2) void k_edge(
    const int* __restrict__ row, const int* __restrict__ col,
    const float* __restrict__ efea,
    const float* __restrict__ W1,
    const float* __restrict__ W2, const float* __restrict__ B2,
    const float* __restrict__ CW1, const float* __restrict__ CB1,
    const float* __restrict__ CW2, const float* __restrict__ CB2) {
    extern __shared__ float sm[];
    float* sW1e = sm;                  // [9][64] PERM4
    float* sW2p = sW1e + 9 * HH;       // [64][64] PERM4
    float* sCW1 = sW2p + HH * HH;      // [64][64] PERM4
    float* sB2  = sCW1 + HH * HH;
    float* sCB1 = sB2 + HH;
    float* sCW2 = sCB1 + HH;
    float* sCB2 = sCW2 + HH;
    float* sStg = sCB2 + 4;            // 8 * 2048

    const int t = threadIdx.x;
    for (int i = t; i < 9 * HH; i += 256) {
        int k = i >> 6, j = i & 63;
        int srcRow = (k == 0) ? 0 : (1 + 2 * HH + (k - 1));
        sW1e[(k << 6) + PERM4(j)] = W1[srcRow * HH + j];
    }
    for (int i = t; i < HH * HH; i += 256) {
        int k = i >> 6, j = i & 63;
        int p = (k << 6) + PERM4(j);
        sW2p[p] = W2[i];
        sCW1[p] = CW1[i];
    }
    for (int i = t; i < HH; i += 256) {
        sB2[i] = B2[i]; sCB1[i] = CB1[i]; sCW2[i] = CW2[i];
    }
    if (t == 0) sCB2[0] = CB2[0];
    __syncthreads();

    const int wid = t >> 5, lane = t & 31;
    const int h = lane & 3, qd = lane >> 2, h4 = h << 2;
    float4* stW = (float4*)(sStg + wid * (HH * 32));  // [64 rows][8 float4]

    const int e0 = blockIdx.x * 256 + (wid << 5) + (qd << 2);
    const int4 rv = *(const int4*)(row + e0);
    const int4 cv = *(const int4*)(col + e0);
    const int r0 = rv.x, r1 = rv.y, r2i = rv.z, r3 = rv.w;
    const int c0 = cv.x, c1 = cv.y, c2 = cv.z, c3 = cv.w;

    const float rx0 = g_x[r0 * 3 + 0] - g_x[c0 * 3 + 0];
    const float ry0 = g_x[r0 * 3 + 1] - g_x[c0 * 3 + 1];
    const float rz0 = g_x[r0 * 3 + 2] - g_x[c0 * 3 + 2];
    const float rx1 = g_x[r1 * 3 + 0] - g_x[c1 * 3 + 0];
    const float ry1 = g_x[r1 * 3 + 1] - g_x[c1 * 3 + 1];
    const float rz1 = g_x[r1 * 3 + 2] - g_x[c1 * 3 + 2];
    const float rx2 = g_x[r2i * 3 + 0] - g_x[c2 * 3 + 0];
    const float ry2 = g_x[r2i * 3 + 1] - g_x[c2 * 3 + 1];
    const float rz2 = g_x[r2i * 3 + 2] - g_x[c2 * 3 + 2];
    const float rx3 = g_x[r3 * 3 + 0] - g_x[c3 * 3 + 0];
    const float ry3 = g_x[r3 * 3 + 1] - g_x[c3 * 3 + 1];
    const float rz3 = g_x[r3 * 3 + 2] - g_x[c3 * 3 + 2];
    const float s2_0 = rx0 * rx0 + ry0 * ry0 + rz0 * rz0;
    const float s2_1 = rx1 * rx1 + ry1 * ry1 + rz1 * rz1;
    const float s2_2 = rx2 * rx2 + ry2 * ry2 + rz2 * rz2;
    const float s2_3 = rx3 * rx3 + ry3 * ry3 + rz3 * rz3;

    float sx, sy, sz;
    if (h == 0)      { sx = rx0; sy = ry0; sz = rz0; }
    else if (h == 1) { sx = rx1; sy = ry1; sz = rz1; }
    else if (h == 2) { sx = rx2; sy = ry2; sz = rz2; }
    else             { sx = rx3; sy = ry3; sz = rz3; }

    u64 a0[8], a1[8], a2[8], a3[8];

    // ---- stage 1 (factored): acc = A[r]+B[c] + r2*w0 + ef@Wef ----
    initAB(a0, r0, c0, h);
    initAB(a1, r1, c1, h);
    initAB(a2, r2i, c2, h);
    initAB(a3, r3, c3, h);
    fmaQuad(a0, a1, a2, a3, pack2(s2_0), pack2(s2_1), pack2(s2_2), pack2(s2_3),
            sW1e + h4);
    {
        const float4* ef0 = (const float4*)(efea + (size_t)e0 * EE);
        const float4* ef1 = (const float4*)(efea + (size_t)(e0 + 1) * EE);
        const float4* ef2 = (const float4*)(efea + (size_t)(e0 + 2) * EE);
        const float4* ef3 = (const float4*)(efea + (size_t)(e0 + 3) * EE);
#pragma unroll
        for (int q = 0; q < 2; q++) {
            float4 u0 = ef0[q], u1 = ef1[q], u2 = ef2[q], u3 = ef3[q];
            fmaQuad(a0, a1, a2, a3, pack2(u0.x), pack2(u1.x), pack2(u2.x), pack2(u3.x),
                    sW1e + ((1 + 4 * q + 0) << 6) + h4);
            fmaQuad(a0, a1, a2, a3, pack2(u0.y), pack2(u1.y), pack2(u2.y), pack2(u3.y),
                    sW1e + ((1 + 4 * q + 1) << 6) + h4);
            fmaQuad(a0, a1, a2, a3, pack2(u0.z), pack2(u1.z), pack2(u2.z), pack2(u3.z),
                    sW1e + ((1 + 4 * q + 2) << 6) + h4);
            fmaQuad(a0, a1, a2, a3, pack2(u0.w), pack2(u1.w), pack2(u2.w), pack2(u3.w),
                    sW1e + ((1 + 4 * q + 3) << 6) + h4);
        }
    }
    {
        float f0[16], f1[16], f2[16], f3[16];
        siluQuarter(a0, f0);
        siluQuarter(a1, f1);
        siluQuarter(a2, f2);
        siluQuarter(a3, f3);
#pragma unroll
        for (int m = 0; m < 16; m++)
            stW[((h << 4) + m) * 8 + qd] = make_float4(f0[m], f1[m], f2[m], f3[m]);
    }
    __syncwarp();

    // ---- stage 2: msg = silu(hid @ W2 + b2), explicit staging prefetch ----
    loadQuarter(a0, sB2, h);
#pragma unroll
    for (int m = 0; m < 8; m++) { a1[m] = a0[m]; a2[m] = a0[m]; a3[m] = a0[m]; }
    {
        float4 s_cur = stW[qd];
#pragma unroll
        for (int k = 0; k < HH; k++) {
            float4 s_nxt = (k < HH - 1) ? stW[(k + 1) * 8 + qd]
                                        : make_float4(0.f, 0.f, 0.f, 0.f);
            fmaQuad(a0, a1, a2, a3, pack2(s_cur.x), pack2(s_cur.y),
                    pack2(s_cur.z), pack2(s_cur.w), sW2p + (k << 6) + h4);
            s_cur = s_nxt;
        }
    }
    __syncwarp();
    {
        float m0[16], m1[16], m2[16], m3[16];
        siluQuarter(a0, m0);
        siluQuarter(a1, m1);
        siluQuarter(a2, m2);
        siluQuarter(a3, m3);
        const int jo = h << 4;
        float* am0 = &g_aggmsg[(size_t)r0 * HH + jo];
        float* am1 = &g_aggmsg[(size_t)r1 * HH + jo];
        float* am2 = &g_aggmsg[(size_t)r2i * HH + jo];
        float* am3 = &g_aggmsg[(size_t)r3 * HH + jo];
#pragma unroll
        for (int c = 0; c < 4; c++) {
            red4(am0 + 4 * c, m0[4 * c], m0[4 * c + 1], m0[4 * c + 2], m0[4 * c + 3]);
            red4(am1 + 4 * c, m1[4 * c], m1[4 * c + 1], m1[4 * c + 2], m1[4 * c + 3]);
            red4(am2 + 4 * c, m2[4 * c], m2[4 * c + 1], m2[4 * c + 2], m2[4 * c + 3]);
            red4(am3 + 4 * c, m3[4 * c], m3[4 * c + 1], m3[4 * c + 2], m3[4 * c + 3]);
        }
#pragma unroll
        for (int m = 0; m < 16; m++)
            stW[((h << 4) + m) * 8 + qd] = make_float4(m0[m], m1[m], m2[m], m3[m]);
    }
    __syncwarp();

    // ---- stage 3: cm = silu(msg @ CW1 + cb1) . CW2 + cb2 ----
    loadQuarter(a0, sCB1, h);
#pragma unroll
    for (int m = 0; m < 8; m++) { a1[m] = a0[m]; a2[m] = a0[m]; a3[m] = a0[m]; }
    {
        float4 s_cur = stW[qd];
#pragma unroll
        for (int k = 0; k < HH; k++) {
            float4 s_nxt = (k < HH - 1) ? stW[(k + 1) * 8 + qd]
                                        : make_float4(0.f, 0.f, 0.f, 0.f);
            fmaQuad(a0, a1, a2, a3, pack2(s_cur.x), pack2(s_cur.y),
                    pack2(s_cur.z), pack2(s_cur.w), sCW1 + (k << 6) + h4);
            s_cur = s_nxt;
        }
    }
    float cm0 = 0.0f, cm1 = 0.0f, cm2 = 0.0f, cm3 = 0.0f;
#pragma unroll
    for (int m = 0; m < 8; m++) {
        const int j = (h << 4) + 2 * m;
        const float wA = sCW2[j], wB = sCW2[j + 1];
        float x, y;
        unpack2(a0[m], x, y); cm0 += silu_f(x) * wA + silu_f(y) * wB;
        unpack2(a1[m], x, y); cm1 += silu_f(x) * wA + silu_f(y) * wB;
        unpack2(a2[m], x, y); cm2 += silu_f(x) * wA + silu_f(y) * wB;
        unpack2(a3[m], x, y); cm3 += silu_f(x) * wA + silu_f(y) * wB;
    }
    cm0 += __shfl_xor_sync(0xffffffffu, cm0, 1);
    cm0 += __shfl_xor_sync(0xffffffffu, cm0, 2);
    cm1 += __shfl_xor_sync(0xffffffffu, cm1, 1);
    cm1 += __shfl_xor_sync(0xffffffffu, cm1, 2);
    cm2 += __shfl_xor_sync(0xffffffffu, cm2, 1);
    cm2 += __shfl_xor_sync(0xffffffffu, cm2, 2);
    cm3 += __shfl_xor_sync(0xffffffffu, cm3, 1);
    cm3 += __shfl_xor_sync(0xffffffffu, cm3, 2);
    const float cb2v = sCB2[0];
    float cm; int re;
    if (h == 0)      { cm = cm0 + cb2v; re = r0; }
    else if (h == 1) { cm = cm1 + cb2v; re = r1; }
    else if (h == 2) { cm = cm2 + cb2v; re = r2i; }
    else             { cm = cm3 + cb2v; re = r3; }
    red4(&g_aggf[(size_t)re * 4], sx * cm, sy * cm, sz * cm, 0.0f);
}

// ---------------- node kernel (pair-split) ----------------
#define NODE_SMEM_FLOATS (2 * HH * HH + HH * HH + 2 * HH)
__global__ __launch_bounds__(128, 3) void k_node(
    const float* __restrict__ h_in, float* __restrict__ h_out,
    const float* __restrict__ NW1, const float* __restrict__ NB1,
    const float* __restrict__ NW2, const float* __restrict__ NB2,
    float* __restrict__ out_x, float* __restrict__ out_h, int writeOut) {
    extern __shared__ float sm[];
    float* sW1 = sm;
    float* sW2 = sW1 + 2 * HH * HH;
    float* sB1 = sW2 + HH * HH;
    float* sB2 = sB1 + HH;
    const int t = threadIdx.x;
    for (int i = t; i < 2 * HH * HH; i += 128) {
        int k = i >> 6, j = i & 63;
        sW1[(k << 6) + PERM(j)] = NW1[i];
    }
    for (int i = t; i < HH * HH; i += 128) {
        int k = i >> 6, j = i & 63;
        sW2[(k << 6) + PERM(j)] = NW2[i];
    }
    for (int i = t; i < HH; i += 128) { sB1[i] = NB1[i]; sB2[i] = NB2[i]; }
    __syncthreads();

    const int lane = t & 31;
    const int h = lane & 1;
    int n0 = (blockIdx.x * 64 + ((t >> 5) << 4) + (lane >> 1)) * 2;
    const bool valid = (n0 < NN);
    if (!valid) n0 = NN - 2;
    const int n1 = n0 + 1;
    const int h4 = h << 2;

    u64 a0[16], a1[16];
    loadHalf(a0, sB1, h);
#pragma unroll
    for (int m = 0; m < 16; m++) a1[m] = a0[m];
    {
        const float4* p0 = (const float4*)(h_in + (size_t)n0 * HH);
        const float4* p1 = (const float4*)(h_in + (size_t)n1 * HH);
#pragma unroll
        for (int q = 0; q < 16; q++) {
            float4 u = p0[q], v = p1[q];
            fmaPair(a0, a1, pack2(u.x), pack2(v.x), sW1 + ((4 * q + 0) << 6) + h4);
            fmaPair(a0, a1, pack2(u.y), pack2(v.y), sW1 + ((4 * q + 1) << 6) + h4);
            fmaPair(a0, a1, pack2(u.z), pack2(v.z), sW1 + ((4 * q + 2) << 6) + h4);
            fmaPair(a0, a1, pack2(u.w), pack2(v.w), sW1 + ((4 * q + 3) << 6) + h4);
        }
        const float4* m0 = (const float4*)(g_aggmsg + (size_t)n0 * HH);
        const float4* m1 = (const float4*)(g_aggmsg + (size_t)n1 * HH);
#pragma unroll
        for (int q = 0; q < 16; q++) {
            float4 u = m0[q], v = m1[q];
            fmaPair(a0, a1, pack2(u.x), pack2(v.x), sW1 + ((HH + 4 * q + 0) << 6) + h4);
            fmaPair(a0, a1, pack2(u.y), pack2(v.y), sW1 + ((HH + 4 * q + 1) << 6) + h4);
            fmaPair(a0, a1, pack2(u.z), pack2(v.z), sW1 + ((HH + 4 * q + 2) << 6) + h4);
            fmaPair(a0, a1, pack2(u.w), pack2(v.w), sW1 + ((HH + 4 * q + 3) << 6) + h4);
        }
    }
    float hid0[32], hid1[32];
    siluHalf(a0, hid0);
    siluHalf(a1, hid1);

    loadHalf(a0, sB2, h);
#pragma unroll
    for (int m = 0; m < 16; m++) a1[m] = a0[m];
#pragma unroll
    for (int k = 0; k < HH; k++) {
        const int src = (lane & ~1) | (k >> 5);
        float s0 = __shfl_sync(0xffffffffu, hid0[k & 31], src);
        float s1 = __shfl_sync(0xffffffffu, hid1[k & 31], src);
        fmaPair(a0, a1, pack2(s0), pack2(s1), sW2 + (k << 6) + h4);
    }

    if (valid) {
        const int jo = h << 5;
        // last layer: write only the harness output; h_out is dead afterwards
        float* dst0 = writeOut ? (out_h + (size_t)n0 * HH + jo)
                               : (h_out + (size_t)n0 * HH + jo);
        float* dst1 = writeOut ? (out_h + (size_t)n1 * HH + jo)
                               : (h_out + (size_t)n1 * HH + jo);
        ulonglong2* o0 = (ulonglong2*)dst0;
        ulonglong2* o1 = (ulonglong2*)dst1;
#pragma unroll
        for (int c = 0; c < 8; c++) {
            o0[c] = make_ulonglong2(a0[2 * c], a0[2 * c + 1]);
            o1[c] = make_ulonglong2(a1[2 * c], a1[2 * c + 1]);
        }
        const int n = n0 + h;
        float cnt = g_cnt[n];
        float inv = 1.0f / fmaxf(cnt, 1.0f);
#pragma unroll
        for (int d = 0; d < 3; d++) {
            float tot = g_aggf[(size_t)n * 4 + d] * inv;
            tot = fminf(fmaxf(tot, -100.0f), 100.0f);
            float nx = g_x[n * 3 + d] + tot;
            g_x[n * 3 + d] = nx;
            if (writeOut) out_x[n * 3 + d] = nx;
        }
    }
}

// ---------------- launch ----------------
extern "C" void kernel_launch(void* const* d_in, const int* in_sizes, int n_in,
                              void* d_out, int out_size) {
    const float* x    = (const float*)d_in[0];
    const float* h    = (const float*)d_in[1];
    const int*   row  = (const int*)d_in[2];
    const int*   col  = (const int*)d_in[3];
    const float* efea = (const float*)d_in[4];
    const float* embW = (const float*)d_in[5];
    const float* embB = (const float*)d_in[6];
    const float* eW1  = (const float*)d_in[7];
    const float* eB1  = (const float*)d_in[8];
    const float* eW2  = (const float*)d_in[9];
    const float* eB2  = (const float*)d_in[10];
    const float* cW1  = (const float*)d_in[11];
    const float* cB1  = (const float*)d_in[12];
    const float* cW2  = (const float*)d_in[13];
    const float* cB2  = (const float*)d_in[14];
    const float* nW1  = (const float*)d_in[15];
    const float* nB1  = (const float*)d_in[16];
    const float* nW2  = (const float*)d_in[17];
    const float* nB2  = (const float*)d_in[18];
    float* out = (float*)d_out;

    void *p_x, *p_h0, *p_h1, *p_am, *p_af, *p_cnt;
    cudaGetSymbolAddress(&p_x, g_x);
    cudaGetSymbolAddress(&p_h0, g_h0);
    cudaGetSymbolAddress(&p_h1, g_h1);
    cudaGetSymbolAddress(&p_am, g_aggmsg);
    cudaGetSymbolAddress(&p_af, g_aggf);
    cudaGetSymbolAddress(&p_cnt, g_cnt);

    const int edge_smem   = EDGE_SMEM_FLOATS * sizeof(float);
    const int node_smem   = NODE_SMEM_FLOATS * sizeof(float);
    const int pre_smem    = PRE_SMEM_FLOATS * sizeof(float);
    const int preemb_smem = PREEMB_SMEM_FLOATS * sizeof(float);
    cudaFuncSetAttribute(k_edge, cudaFuncAttributeMaxDynamicSharedMemorySize, edge_smem);
    cudaFuncSetAttribute(k_node, cudaFuncAttributeMaxDynamicSharedMemorySize, node_smem);
    cudaFuncSetAttribute(k_pre,  cudaFuncAttributeMaxDynamicSharedMemorySize, pre_smem);
    cudaFuncSetAttribute(k_embed_pre, cudaFuncAttributeMaxDynamicSharedMemorySize, preemb_smem);

    cudaMemcpyAsync(p_x, x, NN * 3 * sizeof(float), cudaMemcpyDeviceToDevice, 0);
    cudaMemsetAsync(p_cnt, 0, NN * sizeof(float), 0);
    k_cnt<<<(MM + 255) / 256, 256>>>(row);
    k_embed_pre<<<(NN + 127) / 128, 128, preemb_smem>>>(h, embW, embB, eW1, eB1);

    float* hbuf[2] = {(float*)p_h0, (float*)p_h1};
    float* out_x = out;
    float* out_h = out + (size_t)NN * 3;
    const int node_grid = (NN / 2 + 63) / 64;   // 391

    for (int i = 0; i < LL; i++) {
        cudaMemsetAsync(p_am, 0, (size_t)NN * HH * sizeof(float), 0);
        cudaMemsetAsync(p_af, 0, (size_t)NN * 4 * sizeof(float), 0);
        if (i > 0)
            k_pre<<<(NN + 127) / 128, 128, pre_smem>>>(
                hbuf[i & 1], eW1 + (size_t)i * DIN * HH, eB1 + (size_t)i * HH);
        k_edge<<<MM / 256, 256, edge_smem>>>(
            row, col, efea,
            eW1 + (size_t)i * DIN * HH,
            eW2 + (size_t)i * HH * HH,  eB2 + (size_t)i * HH,
            cW1 + (size_t)i * HH * HH,  cB1 + (size_t)i * HH,
            cW2 + (size_t)i * HH,       cB2 + (size_t)i * 1);
        k_node<<<node_grid, 128, node_smem>>>(
            hbuf[i & 1], hbuf[(i + 1) & 1],
            nW1 + (size_t)i * 2 * HH * HH, nB1 + (size_t)i * HH,
            nW2 + (size_t)i * HH * HH,     nB2 + (size_t)i * HH,
            out_x, out_h, (i == LL - 1) ? 1 : 0);
    }
    (void)in_sizes; (void)n_in; (void)out_size;
}

// round 12
// speedup vs baseline: 1.1079x; 1.0990x over previous
#include <cuda_runtime.h>

#define NN 50000
#define MM 800000
#define HH 64
#define EE 8
#define INN 16
#define DIN 137  // 1 + 2*H + E
#define LL 2

typedef unsigned long long u64;
typedef unsigned int u32;

// ---------------- device scratch (no allocs allowed) ----------------
__device__ float g_h0[NN * HH];
__device__ float g_h1[NN * HH];
__device__ float g_x[NN * 3];
__device__ float g_aggmsg[NN * HH];
__device__ float g_aggf[NN * 4];
__device__ float g_cnt[NN];
__device__ float g_A[NN * HH];     // h @ W1[1:65] + b1
__device__ float g_B[NN * HH];     // h @ W1[65:129]

__device__ __forceinline__ float silu_f(float v) {
    return __fdividef(v, 1.0f + __expf(-v));
}
__device__ __forceinline__ u64 pack2(float s) {
    u64 r; asm("mov.b64 %0, {%1, %1};" : "=l"(r) : "f"(s)); return r;
}
__device__ __forceinline__ void unpack2(u64 v, float& lo, float& hi) {
    asm("mov.b64 {%0, %1}, %2;" : "=f"(lo), "=f"(hi) : "l"(v));
}
__device__ __forceinline__ void fma2(u64& acc, u64 w, u64 s) {
    asm("fma.rn.f32x2 %0, %1, %2, %0;" : "+l"(acc) : "l"(w), "l"(s));
}
__device__ __forceinline__ void add2(u64& acc, u64 v) {
    asm("add.rn.f32x2 %0, %1, %0;" : "+l"(acc) : "l"(v));
}
__device__ __forceinline__ void red4(float* p, float a, float b, float c, float d) {
    asm volatile("red.global.add.v4.f32 [%0], {%1, %2, %3, %4};"
                 :: "l"(p), "f"(a), "f"(b), "f"(c), "f"(d) : "memory");
}

// NATURAL quad ownership: lane h (0..3) owns outputs j = 16c + 4h + o.
// Weight rows stored naturally; lane reads 16B chunks at h*16B + c*64B.

// one k-step for 4 items: 4 LDS.128 + 32 FMA2 (natural layout)
__device__ __forceinline__ void fmaQuad(u64* a0, u64* a1, u64* a2, u64* a3,
                                        u64 s0, u64 s1, u64 s2, u64 s3,
                                        const float* wh) {
#pragma unroll
    for (int c = 0; c < 4; c++) {
        ulonglong2 t = *reinterpret_cast<const ulonglong2*>(wh + (c << 4));
        fma2(a0[2 * c], t.x, s0); fma2(a0[2 * c + 1], t.y, s0);
        fma2(a1[2 * c], t.x, s1); fma2(a1[2 * c + 1], t.y, s1);
        fma2(a2[2 * c], t.x, s2); fma2(a2[2 * c + 1], t.y, s2);
        fma2(a3[2 * c], t.x, s3); fma2(a3[2 * c + 1], t.y, s3);
    }
}
// load lane-h quarter of a 64-float vector (natural interleave)
__device__ __forceinline__ void loadQuarterN(u64* a, const float* b, int h) {
#pragma unroll
    for (int c = 0; c < 4; c++) {
        ulonglong2 v = *reinterpret_cast<const ulonglong2*>(b + (h << 2) + (c << 4));
        a[2 * c] = v.x; a[2 * c + 1] = v.y;
    }
}
__device__ __forceinline__ void siluQuarter(const u64* a, float* f) {
#pragma unroll
    for (int m = 0; m < 8; m++) {
        float x, y; unpack2(a[m], x, y);
        f[2 * m] = silu_f(x); f[2 * m + 1] = silu_f(y);
    }
}
// a = A[r] + B[c], lane-h natural quarter: chunks at h*16B + q*64B (coalesced)
__device__ __forceinline__ void initABN(u64* a, int r, int c, int h) {
    const float* pa = g_A + (size_t)r * HH + (h << 2);
    const float* pb = g_B + (size_t)c * HH + (h << 2);
#pragma unroll
    for (int q = 0; q < 4; q++) {
        ulonglong2 va = *reinterpret_cast<const ulonglong2*>(pa + (q << 4));
        ulonglong2 vb = *reinterpret_cast<const ulonglong2*>(pb + (q << 4));
        add2(va.x, vb.x); add2(va.y, vb.y);
        a[2 * q] = va.x; a[2 * q + 1] = va.y;
    }
}
// ---- broadcast helpers
__device__ __forceinline__ void fmaB(u64* acc, u64 s2, const float* w) {
    const ulonglong2* w2 = reinterpret_cast<const ulonglong2*>(w);
#pragma unroll
    for (int q = 0; q < 16; q++) {
        ulonglong2 t = w2[q];
        fma2(acc[2 * q], t.x, s2); fma2(acc[2 * q + 1], t.y, s2);
    }
}
__device__ __forceinline__ void loadB(u64* acc, const float* b) {
    const ulonglong2* p = reinterpret_cast<const ulonglong2*>(b);
#pragma unroll
    for (int q = 0; q < 16; q++) {
        ulonglong2 v = p[q];
        acc[2 * q] = v.x; acc[2 * q + 1] = v.y;
    }
}
__device__ __forceinline__ void storeB(float* dst, const u64* acc) {
    ulonglong2* p = (ulonglong2*)dst;
#pragma unroll
    for (int q = 0; q < 16; q++)
        p[q] = make_ulonglong2(acc[2 * q], acc[2 * q + 1]);
}

// ---------------- degree count ----------------
__global__ void k_cnt(const int* __restrict__ row) {
    int e = blockIdx.x * blockDim.x + threadIdx.x;
    if (e < MM) atomicAdd(&g_cnt[row[e]], 1.0f);
}

// -------- fused embedding + layer-0 A/B precompute --------
#define PREEMB_SMEM_FLOATS (INN * HH + 2 * HH * HH + 2 * HH)
__global__ __launch_bounds__(128) void k_embed_pre(
    const float* __restrict__ h_in,
    const float* __restrict__ embW, const float* __restrict__ embB,
    const float* __restrict__ W1, const float* __restrict__ B1) {
    extern __shared__ float sm[];
    float* sWe = sm;
    float* sWa = sWe + INN * HH;
    float* sWb = sWa + HH * HH;
    float* sbe = sWb + HH * HH;
    float* sb1 = sbe + HH;
    const int t = threadIdx.x;
    for (int i = t; i < INN * HH; i += 128) sWe[i] = embW[i];
    for (int i = t; i < HH * HH; i += 128) {
        sWa[i] = W1[(1 + (i >> 6)) * HH + (i & 63)];
        sWb[i] = W1[(1 + HH + (i >> 6)) * HH + (i & 63)];
    }
    for (int i = t; i < HH; i += 128) { sbe[i] = embB[i]; sb1[i] = B1[i]; }
    __syncthreads();
    int n = blockIdx.x * 128 + t;
    if (n >= NN) return;
    u64 acc[32];
    loadB(acc, sbe);
    const float4* hv4 = (const float4*)(h_in + (size_t)n * INN);
#pragma unroll
    for (int q = 0; q < INN / 4; q++) {
        float4 v = hv4[q];
        fmaB(acc, pack2(v.x), sWe + (4 * q + 0) * HH);
        fmaB(acc, pack2(v.y), sWe + (4 * q + 1) * HH);
        fmaB(acc, pack2(v.z), sWe + (4 * q + 2) * HH);
        fmaB(acc, pack2(v.w), sWe + (4 * q + 3) * HH);
    }
    storeB(g_h0 + (size_t)n * HH, acc);
    float hv[HH];
#pragma unroll
    for (int q = 0; q < 32; q++) unpack2(acc[q], hv[2 * q], hv[2 * q + 1]);
    loadB(acc, sb1);
#pragma unroll
    for (int k = 0; k < HH; k++) fmaB(acc, pack2(hv[k]), sWa + k * HH);
    storeB(g_A + (size_t)n * HH, acc);
#pragma unroll
    for (int q = 0; q < 32; q++) acc[q] = 0ull;
#pragma unroll
    for (int k = 0; k < HH; k++) fmaB(acc, pack2(hv[k]), sWb + k * HH);
    storeB(g_B + (size_t)n * HH, acc);
}

// ---------------- per-node precompute (layer >= 1) ----------------
#define PRE_SMEM_FLOATS (2 * HH * HH + HH)
__global__ __launch_bounds__(128) void k_pre(const float* __restrict__ h_in,
                                             const float* __restrict__ W1,
                                             const float* __restrict__ B1) {
    extern __shared__ float sm[];
    float* sWa = sm;
    float* sWb = sWa + HH * HH;
    float* sb  = sWb + HH * HH;
    const int t = threadIdx.x;
    for (int i = t; i < HH * HH; i += 128) {
        sWa[i] = W1[(1 + (i >> 6)) * HH + (i & 63)];
        sWb[i] = W1[(1 + HH + (i >> 6)) * HH + (i & 63)];
    }
    for (int i = t; i < HH; i += 128) sb[i] = B1[i];
    __syncthreads();
    int n = blockIdx.x * 128 + t;
    if (n >= NN) return;
    float hv[HH];
    {
        const float4* p = (const float4*)(h_in + (size_t)n * HH);
#pragma unroll
        for (int q = 0; q < 16; q++) {
            float4 v = p[q];
            hv[4 * q] = v.x; hv[4 * q + 1] = v.y;
            hv[4 * q + 2] = v.z; hv[4 * q + 3] = v.w;
        }
    }
    u64 acc[32];
    loadB(acc, sb);
#pragma unroll
    for (int k = 0; k < HH; k++) fmaB(acc, pack2(hv[k]), sWa + k * HH);
    storeB(g_A + (size_t)n * HH, acc);
#pragma unroll
    for (int q = 0; q < 32; q++) acc[q] = 0ull;
#pragma unroll
    for (int k = 0; k < HH; k++) fmaB(acc, pack2(hv[k]), sWb + k * HH);
    storeB(g_B + (size_t)n * HH, acc);
}

// ===== edge kernel: 256 thr, quad-split, natural layout ====================
#define EDGE_SMEM_FLOATS (9 * HH + 2 * HH * HH + 3 * HH + 4 + 8 * HH * 32)

__global__ __launch_bounds__(256, 2) void k_edge(
    const int* __restrict__ row, const int* __restrict__ col,
    const float* __restrict__ efea,
    const float* __restrict__ W1,
    const float* __restrict__ W2, const float* __restrict__ B2,
    const float* __restrict__ CW1, const float* __restrict__ CB1,
    const float* __restrict__ CW2, const float* __restrict__ CB2) {
    extern __shared__ float sm[];
    float* sW1e = sm;                  // [9][64] natural
    float* sW2p = sW1e + 9 * HH;       // [64][64] natural
    float* sCW1 = sW2p + HH * HH;      // [64][64] natural
    float* sB2  = sCW1 + HH * HH;
    float* sCB1 = sB2 + HH;
    float* sCW2 = sCB1 + HH;
    float* sCB2 = sCW2 + HH;
    float* sStg = sCB2 + 4;            // 8 warps * 64 rows * 32 floats

    const int t = threadIdx.x;
    for (int i = t; i < 9 * HH; i += 256) {
        int k = i >> 6, j = i & 63;
        int srcRow = (k == 0) ? 0 : (1 + 2 * HH + (k - 1));
        sW1e[i] = W1[srcRow * HH + j];
    }
    for (int i = t; i < HH * HH; i += 256) {
        sW2p[i] = W2[i];
        sCW1[i] = CW1[i];
    }
    for (int i = t; i < HH; i += 256) {
        sB2[i] = B2[i]; sCB1[i] = CB1[i]; sCW2[i] = CW2[i];
    }
    if (t == 0) sCB2[0] = CB2[0];
    __syncthreads();

    const int wid = t >> 5, lane = t & 31;
    const int h = lane & 3, qd = lane >> 2, h4 = h << 2;
    float4* stW = (float4*)(sStg + wid * (HH * 32));  // [64 rows][8 float4]

    const int e0 = blockIdx.x * 256 + (wid << 5) + (qd << 2);
    const int4 rv = *(const int4*)(row + e0);
    const int4 cv = *(const int4*)(col + e0);
    const int r0 = rv.x, r1 = rv.y, r2i = rv.z, r3 = rv.w;
    const int c0 = cv.x, c1 = cv.y, c2 = cv.z, c3 = cv.w;

    const float rx0 = g_x[r0 * 3 + 0] - g_x[c0 * 3 + 0];
    const float ry0 = g_x[r0 * 3 + 1] - g_x[c0 * 3 + 1];
    const float rz0 = g_x[r0 * 3 + 2] - g_x[c0 * 3 + 2];
    const float rx1 = g_x[r1 * 3 + 0] - g_x[c1 * 3 + 0];
    const float ry1 = g_x[r1 * 3 + 1] - g_x[c1 * 3 + 1];
    const float rz1 = g_x[r1 * 3 + 2] - g_x[c1 * 3 + 2];
    const float rx2 = g_x[r2i * 3 + 0] - g_x[c2 * 3 + 0];
    const float ry2 = g_x[r2i * 3 + 1] - g_x[c2 * 3 + 1];
    const float rz2 = g_x[r2i * 3 + 2] - g_x[c2 * 3 + 2];
    const float rx3 = g_x[r3 * 3 + 0] - g_x[c3 * 3 + 0];
    const float ry3 = g_x[r3 * 3 + 1] - g_x[c3 * 3 + 1];
    const float rz3 = g_x[r3 * 3 + 2] - g_x[c3 * 3 + 2];
    const float s2_0 = rx0 * rx0 + ry0 * ry0 + rz0 * rz0;
    const float s2_1 = rx1 * rx1 + ry1 * ry1 + rz1 * rz1;
    const float s2_2 = rx2 * rx2 + ry2 * ry2 + rz2 * rz2;
    const float s2_3 = rx3 * rx3 + ry3 * ry3 + rz3 * rz3;

    float sx, sy, sz;
    if (h == 0)      { sx = rx0; sy = ry0; sz = rz0; }
    else if (h == 1) { sx = rx1; sy = ry1; sz = rz1; }
    else if (h == 2) { sx = rx2; sy = ry2; sz = rz2; }
    else             { sx = rx3; sy = ry3; sz = rz3; }

    u64 a0[8], a1[8], a2[8], a3[8];

    // ---- stage 1 (factored): acc = A[r]+B[c] + r2*w0 + ef@Wef ----
    initABN(a0, r0, c0, h);
    initABN(a1, r1, c1, h);
    initABN(a2, r2i, c2, h);
    initABN(a3, r3, c3, h);
    fmaQuad(a0, a1, a2, a3, pack2(s2_0), pack2(s2_1), pack2(s2_2), pack2(s2_3),
            sW1e + h4);
    {
        const float4* ef0 = (const float4*)(efea + (size_t)e0 * EE);
        const float4* ef1 = (const float4*)(efea + (size_t)(e0 + 1) * EE);
        const float4* ef2 = (const float4*)(efea + (size_t)(e0 + 2) * EE);
        const float4* ef3 = (const float4*)(efea + (size_t)(e0 + 3) * EE);
#pragma unroll
        for (int q = 0; q < 2; q++) {
            float4 u0 = ef0[q], u1 = ef1[q], u2 = ef2[q], u3 = ef3[q];
            fmaQuad(a0, a1, a2, a3, pack2(u0.x), pack2(u1.x), pack2(u2.x), pack2(u3.x),
                    sW1e + ((1 + 4 * q + 0) << 6) + h4);
            fmaQuad(a0, a1, a2, a3, pack2(u0.y), pack2(u1.y), pack2(u2.y), pack2(u3.y),
                    sW1e + ((1 + 4 * q + 1) << 6) + h4);
            fmaQuad(a0, a1, a2, a3, pack2(u0.z), pack2(u1.z), pack2(u2.z), pack2(u3.z),
                    sW1e + ((1 + 4 * q + 2) << 6) + h4);
            fmaQuad(a0, a1, a2, a3, pack2(u0.w), pack2(u1.w), pack2(u2.w), pack2(u3.w),
                    sW1e + ((1 + 4 * q + 3) << 6) + h4);
        }
    }
    // silu + stage hid: value index i = 4c+o -> hid index j = 16c+4h+o
    {
        float f0[16], f1[16], f2[16], f3[16];
        siluQuarter(a0, f0);
        siluQuarter(a1, f1);
        siluQuarter(a2, f2);
        siluQuarter(a3, f3);
#pragma unroll
        for (int i = 0; i < 16; i++) {
            int rowj = ((i >> 2) << 4) + (h << 2) + (i & 3);
            stW[rowj * 8 + qd] = make_float4(f0[i], f1[i], f2[i], f3[i]);
        }
    }
    __syncwarp();

    // ---- stage 2: msg = silu(hid @ W2 + b2) ----
    loadQuarterN(a0, sB2, h);
#pragma unroll
    for (int m = 0; m < 8; m++) { a1[m] = a0[m]; a2[m] = a0[m]; a3[m] = a0[m]; }
#pragma unroll
    for (int k = 0; k < HH; k++) {
        float4 s = stW[k * 8 + qd];
        fmaQuad(a0, a1, a2, a3, pack2(s.x), pack2(s.y), pack2(s.z), pack2(s.w),
                sW2p + (k << 6) + h4);
    }
    __syncwarp();
    {
        float m0[16], m1[16], m2[16], m3[16];
        siluQuarter(a0, m0);
        siluQuarter(a1, m1);
        siluQuarter(a2, m2);
        siluQuarter(a3, m3);
        float* am0 = &g_aggmsg[(size_t)r0 * HH];
        float* am1 = &g_aggmsg[(size_t)r1 * HH];
        float* am2 = &g_aggmsg[(size_t)r2i * HH];
        float* am3 = &g_aggmsg[(size_t)r3 * HH];
#pragma unroll
        for (int c = 0; c < 4; c++) {
            const int off = (c << 4) + (h << 2);
            red4(am0 + off, m0[4 * c], m0[4 * c + 1], m0[4 * c + 2], m0[4 * c + 3]);
            red4(am1 + off, m1[4 * c], m1[4 * c + 1], m1[4 * c + 2], m1[4 * c + 3]);
            red4(am2 + off, m2[4 * c], m2[4 * c + 1], m2[4 * c + 2], m2[4 * c + 3]);
            red4(am3 + off, m3[4 * c], m3[4 * c + 1], m3[4 * c + 2], m3[4 * c + 3]);
        }
#pragma unroll
        for (int i = 0; i < 16; i++) {
            int rowj = ((i >> 2) << 4) + (h << 2) + (i & 3);
            stW[rowj * 8 + qd] = make_float4(m0[i], m1[i], m2[i], m3[i]);
        }
    }
    __syncwarp();

    // ---- stage 3: cm = silu(msg @ CW1 + cb1) . CW2 + cb2 ----
    loadQuarterN(a0, sCB1, h);
#pragma unroll
    for (int m = 0; m < 8; m++) { a1[m] = a0[m]; a2[m] = a0[m]; a3[m] = a0[m]; }
#pragma unroll
    for (int k = 0; k < HH; k++) {
        float4 s = stW[k * 8 + qd];
        fmaQuad(a0, a1, a2, a3, pack2(s.x), pack2(s.y), pack2(s.z), pack2(s.w),
                sCW1 + (k << 6) + h4);
    }
    float cm0 = 0.0f, cm1 = 0.0f, cm2 = 0.0f, cm3 = 0.0f;
#pragma unroll
    for (int m = 0; m < 8; m++) {
        const int j = ((m >> 1) << 4) + (h << 2) + ((m & 1) << 1);
        const float wA = sCW2[j], wB = sCW2[j + 1];
        float x, y;
        unpack2(a0[m], x, y); cm0 += silu_f(x) * wA + silu_f(y) * wB;
        unpack2(a1[m], x, y); cm1 += silu_f(x) * wA + silu_f(y) * wB;
        unpack2(a2[m], x, y); cm2 += silu_f(x) * wA + silu_f(y) * wB;
        unpack2(a3[m], x, y); cm3 += silu_f(x) * wA + silu_f(y) * wB;
    }
    cm0 += __shfl_xor_sync(0xffffffffu, cm0, 1);
    cm0 += __shfl_xor_sync(0xffffffffu, cm0, 2);
    cm1 += __shfl_xor_sync(0xffffffffu, cm1, 1);
    cm1 += __shfl_xor_sync(0xffffffffu, cm1, 2);
    cm2 += __shfl_xor_sync(0xffffffffu, cm2, 1);
    cm2 += __shfl_xor_sync(0xffffffffu, cm2, 2);
    cm3 += __shfl_xor_sync(0xffffffffu, cm3, 1);
    cm3 += __shfl_xor_sync(0xffffffffu, cm3, 2);
    const float cb2v = sCB2[0];
    float cm; int re;
    if (h == 0)      { cm = cm0 + cb2v; re = r0; }
    else if (h == 1) { cm = cm1 + cb2v; re = r1; }
    else if (h == 2) { cm = cm2 + cb2v; re = r2i; }
    else             { cm = cm3 + cb2v; re = r3; }
    red4(&g_aggf[(size_t)re * 4], sx * cm, sy * cm, sz * cm, 0.0f);
}

// ---------------- node kernel: QUAD-split, natural layout ----------------
#define NODE_SMEM_FLOATS (2 * HH * HH + HH * HH + 2 * HH)
__global__ __launch_bounds__(128, 3) void k_node(
    const float* __restrict__ h_in, float* __restrict__ h_out,
    const float* __restrict__ NW1, const float* __restrict__ NB1,
    const float* __restrict__ NW2, const float* __restrict__ NB2,
    float* __restrict__ out_x, float* __restrict__ out_h, int writeOut) {
    extern __shared__ float sm[];
    float* sW1 = sm;                  // [128][64] natural
    float* sW2 = sW1 + 2 * HH * HH;   // [64][64] natural
    float* sB1 = sW2 + HH * HH;
    float* sB2 = sB1 + HH;
    const int t = threadIdx.x;
    for (int i = t; i < 2 * HH * HH; i += 128) sW1[i] = NW1[i];
    for (int i = t; i < HH * HH; i += 128) sW2[i] = NW2[i];
    for (int i = t; i < HH; i += 128) { sB1[i] = NB1[i]; sB2[i] = NB2[i]; }
    __syncthreads();

    const int wid = t >> 5, lane = t & 31;
    const int h = lane & 3, qd = lane >> 2, h4 = h << 2;
    // quad handles 4 consecutive nodes; clamp (duplicates write identical data)
    int n0 = blockIdx.x * 128 + (wid << 5) + (qd << 2);
    if (n0 + 3 >= NN) n0 = NN - 4;

    u64 a0[8], a1[8], a2[8], a3[8];
    loadQuarterN(a0, sB1, h);
#pragma unroll
    for (int m = 0; m < 8; m++) { a1[m] = a0[m]; a2[m] = a0[m]; a3[m] = a0[m]; }
    {
        const float4* p0 = (const float4*)(h_in + (size_t)n0 * HH);
        const float4* p1 = (const float4*)(h_in + (size_t)(n0 + 1) * HH);
        const float4* p2 = (const float4*)(h_in + (size_t)(n0 + 2) * HH);
        const float4* p3 = (const float4*)(h_in + (size_t)(n0 + 3) * HH);
#pragma unroll
        for (int q = 0; q < 16; q++) {
            float4 u0 = p0[q], u1 = p1[q], u2 = p2[q], u3 = p3[q];
            fmaQuad(a0, a1, a2, a3, pack2(u0.x), pack2(u1.x), pack2(u2.x), pack2(u3.x),
                    sW1 + ((4 * q + 0) << 6) + h4);
            fmaQuad(a0, a1, a2, a3, pack2(u0.y), pack2(u1.y), pack2(u2.y), pack2(u3.y),
                    sW1 + ((4 * q + 1) << 6) + h4);
            fmaQuad(a0, a1, a2, a3, pack2(u0.z), pack2(u1.z), pack2(u2.z), pack2(u3.z),
                    sW1 + ((4 * q + 2) << 6) + h4);
            fmaQuad(a0, a1, a2, a3, pack2(u0.w), pack2(u1.w), pack2(u2.w), pack2(u3.w),
                    sW1 + ((4 * q + 3) << 6) + h4);
        }
        const float4* m0 = (const float4*)(g_aggmsg + (size_t)n0 * HH);
        const float4* m1 = (const float4*)(g_aggmsg + (size_t)(n0 + 1) * HH);
        const float4* m2 = (const float4*)(g_aggmsg + (size_t)(n0 + 2) * HH);
        const float4* m3 = (const float4*)(g_aggmsg + (size_t)(n0 + 3) * HH);
#pragma unroll
        for (int q = 0; q < 16; q++) {
            float4 u0 = m0[q], u1 = m1[q], u2 = m2[q], u3 = m3[q];
            fmaQuad(a0, a1, a2, a3, pack2(u0.x), pack2(u1.x), pack2(u2.x), pack2(u3.x),
                    sW1 + ((HH + 4 * q + 0) << 6) + h4);
            fmaQuad(a0, a1, a2, a3, pack2(u0.y), pack2(u1.y), pack2(u2.y), pack2(u3.y),
                    sW1 + ((HH + 4 * q + 1) << 6) + h4);
            fmaQuad(a0, a1, a2, a3, pack2(u0.z), pack2(u1.z), pack2(u2.z), pack2(u3.z),
                    sW1 + ((HH + 4 * q + 2) << 6) + h4);
            fmaQuad(a0, a1, a2, a3, pack2(u0.w), pack2(u1.w), pack2(u2.w), pack2(u3.w),
                    sW1 + ((HH + 4 * q + 3) << 6) + h4);
        }
    }
    // silu -> lane's hid values: index i=4c+o corresponds to j=16c+4h+o
    float hid0[16], hid1[16], hid2[16], hid3[16];
    siluQuarter(a0, hid0);
    siluQuarter(a1, hid1);
    siluQuarter(a2, hid2);
    siluQuarter(a3, hid3);

    loadQuarterN(a0, sB2, h);
#pragma unroll
    for (int m = 0; m < 8; m++) { a1[m] = a0[m]; a2[m] = a0[m]; a3[m] = a0[m]; }
    // hid[k] owned by lane (k>>2)&3 at register index ((k>>4)<<2)+(k&3)
#pragma unroll
    for (int k = 0; k < HH; k++) {
        const int src = (lane & ~3) | ((k >> 2) & 3);
        const int mi = ((k >> 4) << 2) + (k & 3);
        float s0 = __shfl_sync(0xffffffffu, hid0[mi], src);
        float s1 = __shfl_sync(0xffffffffu, hid1[mi], src);
        float s2 = __shfl_sync(0xffffffffu, hid2[mi], src);
        float s3 = __shfl_sync(0xffffffffu, hid3[mi], src);
        fmaQuad(a0, a1, a2, a3, pack2(s0), pack2(s1), pack2(s2), pack2(s3),
                sW2 + (k << 6) + h4);
    }

    // write outputs: lane's chunk c of node i at [n][16c+4h .. +3]
    {
        float* base = writeOut ? out_h : h_out;
        const u64* as[4] = {a0, a1, a2, a3};
#pragma unroll
        for (int i = 0; i < 4; i++) {
            float* dst = base + (size_t)(n0 + i) * HH + h4;
#pragma unroll
            for (int c = 0; c < 4; c++) {
                float x0, y0, x1, y1;
                unpack2(as[i][2 * c], x0, y0);
                unpack2(as[i][2 * c + 1], x1, y1);
                *(float4*)(dst + (c << 4)) = make_float4(x0, y0, x1, y1);
            }
        }
    }
    // coord update: lane h handles node n0+h
    {
        const int n = n0 + h;
        float cnt = g_cnt[n];
        float inv = 1.0f / fmaxf(cnt, 1.0f);
#pragma unroll
        for (int d = 0; d < 3; d++) {
            float tot = g_aggf[(size_t)n * 4 + d] * inv;
            tot = fminf(fmaxf(tot, -100.0f), 100.0f);
            float nx = g_x[n * 3 + d] + tot;
            g_x[n * 3 + d] = nx;
            if (writeOut) out_x[n * 3 + d] = nx;
        }
    }
}

// ---------------- launch ----------------
extern "C" void kernel_launch(void* const* d_in, const int* in_sizes, int n_in,
                              void* d_out, int out_size) {
    const float* x    = (const float*)d_in[0];
    const float* h    = (const float*)d_in[1];
    const int*   row  = (const int*)d_in[2];
    const int*   col  = (const int*)d_in[3];
    const float* efea = (const float*)d_in[4];
    const float* embW = (const float*)d_in[5];
    const float* embB = (const float*)d_in[6];
    const float* eW1  = (const float*)d_in[7];
    const float* eB1  = (const float*)d_in[8];
    const float* eW2  = (const float*)d_in[9];
    const float* eB2  = (const float*)d_in[10];
    const float* cW1  = (const float*)d_in[11];
    const float* cB1  = (const float*)d_in[12];
    const float* cW2  = (const float*)d_in[13];
    const float* cB2  = (const float*)d_in[14];
    const float* nW1  = (const float*)d_in[15];
    const float* nB1  = (const float*)d_in[16];
    const float* nW2  = (const float*)d_in[17];
    const float* nB2  = (const float*)d_in[18];
    float* out = (float*)d_out;

    void *p_x, *p_h0, *p_h1, *p_am, *p_af, *p_cnt;
    cudaGetSymbolAddress(&p_x, g_x);
    cudaGetSymbolAddress(&p_h0, g_h0);
    cudaGetSymbolAddress(&p_h1, g_h1);
    cudaGetSymbolAddress(&p_am, g_aggmsg);
    cudaGetSymbolAddress(&p_af, g_aggf);
    cudaGetSymbolAddress(&p_cnt, g_cnt);

    const int edge_smem   = EDGE_SMEM_FLOATS * sizeof(float);
    const int node_smem   = NODE_SMEM_FLOATS * sizeof(float);
    const int pre_smem    = PRE_SMEM_FLOATS * sizeof(float);
    const int preemb_smem = PREEMB_SMEM_FLOATS * sizeof(float);
    cudaFuncSetAttribute(k_edge, cudaFuncAttributeMaxDynamicSharedMemorySize, edge_smem);
    cudaFuncSetAttribute(k_node, cudaFuncAttributeMaxDynamicSharedMemorySize, node_smem);
    cudaFuncSetAttribute(k_pre,  cudaFuncAttributeMaxDynamicSharedMemorySize, pre_smem);
    cudaFuncSetAttribute(k_embed_pre, cudaFuncAttributeMaxDynamicSharedMemorySize, preemb_smem);

    cudaMemcpyAsync(p_x, x, NN * 3 * sizeof(float), cudaMemcpyDeviceToDevice, 0);
    cudaMemsetAsync(p_cnt, 0, NN * sizeof(float), 0);
    k_cnt<<<(MM + 255) / 256, 256>>>(row);
    k_embed_pre<<<(NN + 127) / 128, 128, preemb_smem>>>(h, embW, embB, eW1, eB1);

    float* hbuf[2] = {(float*)p_h0, (float*)p_h1};
    float* out_x = out;
    float* out_h = out + (size_t)NN * 3;
    const int node_grid = (NN + 127) / 128;   // 391

    for (int i = 0; i < LL; i++) {
        cudaMemsetAsync(p_am, 0, (size_t)NN * HH * sizeof(float), 0);
        cudaMemsetAsync(p_af, 0, (size_t)NN * 4 * sizeof(float), 0);
        if (i > 0)
            k_pre<<<(NN + 127) / 128, 128, pre_smem>>>(
                hbuf[i & 1], eW1 + (size_t)i * DIN * HH, eB1 + (size_t)i * HH);
        k_edge<<<MM / 256, 256, edge_smem>>>(
            row, col, efea,
            eW1 + (size_t)i * DIN * HH,
            eW2 + (size_t)i * HH * HH,  eB2 + (size_t)i * HH,
            cW1 + (size_t)i * HH * HH,  cB1 + (size_t)i * HH,
            cW2 + (size_t)i * HH,       cB2 + (size_t)i * 1);
        k_node<<<node_grid, 128, node_smem>>>(
            hbuf[i & 1], hbuf[(i + 1) & 1],
            nW1 + (size_t)i * 2 * HH * HH, nB1 + (size_t)i * HH,
            nW2 + (size_t)i * HH * HH,     nB2 + (size_t)i * HH,
            out_x, out_h, (i == LL - 1) ? 1 : 0);
    }
    (void)in_sizes; (void)n_in; (void)out_size;
}

// round 13
// speedup vs baseline: 1.1348x; 1.0242x over previous
#include <cuda_runtime.h>

#define NN 50000
#define MM 800000
#define HH 64
#define EE 8
#define INN 16
#define DIN 137  // 1 + 2*H + E
#define LL 2

typedef unsigned long long u64;
typedef unsigned int u32;

// ---------------- device scratch (no allocs allowed) ----------------
__device__ float g_h0[NN * HH];
__device__ float g_h1[NN * HH];
__device__ float4 g_x4[NN];        // packed positions (w unused)
__device__ float g_aggmsg[NN * HH];
__device__ float g_aggf[NN * 4];
__device__ float g_cnt[NN];
__device__ float g_A[NN * HH];     // h @ W1[1:65] + b1
__device__ float g_B[NN * HH];     // h @ W1[65:129]

__device__ __forceinline__ float silu_f(float v) {
    return __fdividef(v, 1.0f + __expf(-v));
}
__device__ __forceinline__ u64 pack2(float s) {
    u64 r; asm("mov.b64 %0, {%1, %1};" : "=l"(r) : "f"(s)); return r;
}
__device__ __forceinline__ void unpack2(u64 v, float& lo, float& hi) {
    asm("mov.b64 {%0, %1}, %2;" : "=f"(lo), "=f"(hi) : "l"(v));
}
__device__ __forceinline__ void fma2(u64& acc, u64 w, u64 s) {
    asm("fma.rn.f32x2 %0, %1, %2, %0;" : "+l"(acc) : "l"(w), "l"(s));
}
__device__ __forceinline__ void add2(u64& acc, u64 v) {
    asm("add.rn.f32x2 %0, %1, %0;" : "+l"(acc) : "l"(v));
}
__device__ __forceinline__ void red4(float* p, float a, float b, float c, float d) {
    asm volatile("red.global.add.v4.f32 [%0], {%1, %2, %3, %4};"
                 :: "l"(p), "f"(a), "f"(b), "f"(c), "f"(d) : "memory");
}

// NATURAL quad ownership: lane h (0..3) owns outputs j = 16c + 4h + o.

// one k-step for 4 items: 4 LDS.128 + 32 FMA2 (natural layout)
__device__ __forceinline__ void fmaQuad(u64* a0, u64* a1, u64* a2, u64* a3,
                                        u64 s0, u64 s1, u64 s2, u64 s3,
                                        const float* wh) {
#pragma unroll
    for (int c = 0; c < 4; c++) {
        ulonglong2 t = *reinterpret_cast<const ulonglong2*>(wh + (c << 4));
        fma2(a0[2 * c], t.x, s0); fma2(a0[2 * c + 1], t.y, s0);
        fma2(a1[2 * c], t.x, s1); fma2(a1[2 * c + 1], t.y, s1);
        fma2(a2[2 * c], t.x, s2); fma2(a2[2 * c + 1], t.y, s2);
        fma2(a3[2 * c], t.x, s3); fma2(a3[2 * c + 1], t.y, s3);
    }
}
__device__ __forceinline__ void loadQuarterN(u64* a, const float* b, int h) {
#pragma unroll
    for (int c = 0; c < 4; c++) {
        ulonglong2 v = *reinterpret_cast<const ulonglong2*>(b + (h << 2) + (c << 4));
        a[2 * c] = v.x; a[2 * c + 1] = v.y;
    }
}
__device__ __forceinline__ void siluQuarter(const u64* a, float* f) {
#pragma unroll
    for (int m = 0; m < 8; m++) {
        float x, y; unpack2(a[m], x, y);
        f[2 * m] = silu_f(x); f[2 * m + 1] = silu_f(y);
    }
}
__device__ __forceinline__ void initABN(u64* a, int r, int c, int h) {
    const float* pa = g_A + (size_t)r * HH + (h << 2);
    const float* pb = g_B + (size_t)c * HH + (h << 2);
#pragma unroll
    for (int q = 0; q < 4; q++) {
        ulonglong2 va = *reinterpret_cast<const ulonglong2*>(pa + (q << 4));
        ulonglong2 vb = *reinterpret_cast<const ulonglong2*>(pb + (q << 4));
        add2(va.x, vb.x); add2(va.y, vb.y);
        a[2 * q] = va.x; a[2 * q + 1] = va.y;
    }
}
// ---- broadcast helpers
__device__ __forceinline__ void fmaB(u64* acc, u64 s2, const float* w) {
    const ulonglong2* w2 = reinterpret_cast<const ulonglong2*>(w);
#pragma unroll
    for (int q = 0; q < 16; q++) {
        ulonglong2 t = w2[q];
        fma2(acc[2 * q], t.x, s2); fma2(acc[2 * q + 1], t.y, s2);
    }
}
__device__ __forceinline__ void loadB(u64* acc, const float* b) {
    const ulonglong2* p = reinterpret_cast<const ulonglong2*>(b);
#pragma unroll
    for (int q = 0; q < 16; q++) {
        ulonglong2 v = p[q];
        acc[2 * q] = v.x; acc[2 * q + 1] = v.y;
    }
}
__device__ __forceinline__ void storeB(float* dst, const u64* acc) {
    ulonglong2* p = (ulonglong2*)dst;
#pragma unroll
    for (int q = 0; q < 16; q++)
        p[q] = make_ulonglong2(acc[2 * q], acc[2 * q + 1]);
}

// ---------------- init kernels ----------------
__global__ void k_cnt(const int* __restrict__ row) {
    int e = blockIdx.x * blockDim.x + threadIdx.x;
    if (e < MM) atomicAdd(&g_cnt[row[e]], 1.0f);
}
__global__ void k_packx(const float* __restrict__ x) {
    int n = blockIdx.x * blockDim.x + threadIdx.x;
    if (n < NN)
        g_x4[n] = make_float4(x[n * 3], x[n * 3 + 1], x[n * 3 + 2], 0.0f);
}

// -------- fused embedding + layer-0 A/B precompute --------
#define PREEMB_SMEM_FLOATS (INN * HH + 2 * HH * HH + 2 * HH)
__global__ __launch_bounds__(128) void k_embed_pre(
    const float* __restrict__ h_in,
    const float* __restrict__ embW, const float* __restrict__ embB,
    const float* __restrict__ W1, const float* __restrict__ B1) {
    extern __shared__ float sm[];
    float* sWe = sm;
    float* sWa = sWe + INN * HH;
    float* sWb = sWa + HH * HH;
    float* sbe = sWb + HH * HH;
    float* sb1 = sbe + HH;
    const int t = threadIdx.x;
    for (int i = t; i < INN * HH; i += 128) sWe[i] = embW[i];
    for (int i = t; i < HH * HH; i += 128) {
        sWa[i] = W1[(1 + (i >> 6)) * HH + (i & 63)];
        sWb[i] = W1[(1 + HH + (i >> 6)) * HH + (i & 63)];
    }
    for (int i = t; i < HH; i += 128) { sbe[i] = embB[i]; sb1[i] = B1[i]; }
    __syncthreads();
    int n = blockIdx.x * 128 + t;
    if (n >= NN) return;
    u64 acc[32];
    loadB(acc, sbe);
    const float4* hv4 = (const float4*)(h_in + (size_t)n * INN);
#pragma unroll
    for (int q = 0; q < INN / 4; q++) {
        float4 v = hv4[q];
        fmaB(acc, pack2(v.x), sWe + (4 * q + 0) * HH);
        fmaB(acc, pack2(v.y), sWe + (4 * q + 1) * HH);
        fmaB(acc, pack2(v.z), sWe + (4 * q + 2) * HH);
        fmaB(acc, pack2(v.w), sWe + (4 * q + 3) * HH);
    }
    storeB(g_h0 + (size_t)n * HH, acc);
    float hv[HH];
#pragma unroll
    for (int q = 0; q < 32; q++) unpack2(acc[q], hv[2 * q], hv[2 * q + 1]);
    loadB(acc, sb1);
#pragma unroll
    for (int k = 0; k < HH; k++) fmaB(acc, pack2(hv[k]), sWa + k * HH);
    storeB(g_A + (size_t)n * HH, acc);
#pragma unroll
    for (int q = 0; q < 32; q++) acc[q] = 0ull;
#pragma unroll
    for (int k = 0; k < HH; k++) fmaB(acc, pack2(hv[k]), sWb + k * HH);
    storeB(g_B + (size_t)n * HH, acc);
}

// ---------------- per-node precompute (layer >= 1) ----------------
#define PRE_SMEM_FLOATS (2 * HH * HH + HH)
__global__ __launch_bounds__(128) void k_pre(const float* __restrict__ h_in,
                                             const float* __restrict__ W1,
                                             const float* __restrict__ B1) {
    extern __shared__ float sm[];
    float* sWa = sm;
    float* sWb = sWa + HH * HH;
    float* sb  = sWb + HH * HH;
    const int t = threadIdx.x;
    for (int i = t; i < HH * HH; i += 128) {
        sWa[i] = W1[(1 + (i >> 6)) * HH + (i & 63)];
        sWb[i] = W1[(1 + HH + (i >> 6)) * HH + (i & 63)];
    }
    for (int i = t; i < HH; i += 128) sb[i] = B1[i];
    __syncthreads();
    int n = blockIdx.x * 128 + t;
    if (n >= NN) return;
    float hv[HH];
    {
        const float4* p = (const float4*)(h_in + (size_t)n * HH);
#pragma unroll
        for (int q = 0; q < 16; q++) {
            float4 v = p[q];
            hv[4 * q] = v.x; hv[4 * q + 1] = v.y;
            hv[4 * q + 2] = v.z; hv[4 * q + 3] = v.w;
        }
    }
    u64 acc[32];
    loadB(acc, sb);
#pragma unroll
    for (int k = 0; k < HH; k++) fmaB(acc, pack2(hv[k]), sWa + k * HH);
    storeB(g_A + (size_t)n * HH, acc);
#pragma unroll
    for (int q = 0; q < 32; q++) acc[q] = 0ull;
#pragma unroll
    for (int k = 0; k < HH; k++) fmaB(acc, pack2(hv[k]), sWb + k * HH);
    storeB(g_B + (size_t)n * HH, acc);
}

// ===== edge kernel: 256 thr, quad-split, natural layout, packed x =========
#define EDGE_SMEM_FLOATS (9 * HH + 2 * HH * HH + 3 * HH + 4 + 8 * HH * 32)

__global__ __launch_bounds__(256, 2) void k_edge(
    const int* __restrict__ row, const int* __restrict__ col,
    const float* __restrict__ efea,
    const float* __restrict__ W1,
    const float* __restrict__ W2, const float* __restrict__ B2,
    const float* __restrict__ CW1, const float* __restrict__ CB1,
    const float* __restrict__ CW2, const float* __restrict__ CB2) {
    extern __shared__ float sm[];
    float* sW1e = sm;                  // [9][64] natural
    float* sW2p = sW1e + 9 * HH;       // [64][64] natural
    float* sCW1 = sW2p + HH * HH;      // [64][64] natural
    float* sB2  = sCW1 + HH * HH;
    float* sCB1 = sB2 + HH;
    float* sCW2 = sCB1 + HH;
    float* sCB2 = sCW2 + HH;
    float* sStg = sCB2 + 4;            // 8 warps * 64 rows * 32 floats

    const int t = threadIdx.x;
    for (int i = t; i < 9 * HH; i += 256) {
        int k = i >> 6, j = i & 63;
        int srcRow = (k == 0) ? 0 : (1 + 2 * HH + (k - 1));
        sW1e[i] = W1[srcRow * HH + j];
    }
    for (int i = t; i < HH * HH; i += 256) {
        sW2p[i] = W2[i];
        sCW1[i] = CW1[i];
    }
    for (int i = t; i < HH; i += 256) {
        sB2[i] = B2[i]; sCB1[i] = CB1[i]; sCW2[i] = CW2[i];
    }
    if (t == 0) sCB2[0] = CB2[0];
    __syncthreads();

    const int wid = t >> 5, lane = t & 31;
    const int h = lane & 3, qd = lane >> 2, h4 = h << 2;
    float4* stW = (float4*)(sStg + wid * (HH * 32));  // [64 rows][8 float4]

    const int e0 = blockIdx.x * 256 + (wid << 5) + (qd << 2);
    const int4 rv = *(const int4*)(row + e0);
    const int4 cv = *(const int4*)(col + e0);
    const int r0 = rv.x, r1 = rv.y, r2i = rv.z, r3 = rv.w;
    const int c0 = cv.x, c1 = cv.y, c2 = cv.z, c3 = cv.w;

    const float4 xr0 = g_x4[r0], xc0 = g_x4[c0];
    const float4 xr1 = g_x4[r1], xc1 = g_x4[c1];
    const float4 xr2 = g_x4[r2i], xc2 = g_x4[c2];
    const float4 xr3 = g_x4[r3], xc3 = g_x4[c3];
    const float rx0 = xr0.x - xc0.x, ry0 = xr0.y - xc0.y, rz0 = xr0.z - xc0.z;
    const float rx1 = xr1.x - xc1.x, ry1 = xr1.y - xc1.y, rz1 = xr1.z - xc1.z;
    const float rx2 = xr2.x - xc2.x, ry2 = xr2.y - xc2.y, rz2 = xr2.z - xc2.z;
    const float rx3 = xr3.x - xc3.x, ry3 = xr3.y - xc3.y, rz3 = xr3.z - xc3.z;
    const float s2_0 = rx0 * rx0 + ry0 * ry0 + rz0 * rz0;
    const float s2_1 = rx1 * rx1 + ry1 * ry1 + rz1 * rz1;
    const float s2_2 = rx2 * rx2 + ry2 * ry2 + rz2 * rz2;
    const float s2_3 = rx3 * rx3 + ry3 * ry3 + rz3 * rz3;

    float sx, sy, sz;
    if (h == 0)      { sx = rx0; sy = ry0; sz = rz0; }
    else if (h == 1) { sx = rx1; sy = ry1; sz = rz1; }
    else if (h == 2) { sx = rx2; sy = ry2; sz = rz2; }
    else             { sx = rx3; sy = ry3; sz = rz3; }

    u64 a0[8], a1[8], a2[8], a3[8];

    // ---- stage 1 (factored): acc = A[r]+B[c] + r2*w0 + ef@Wef ----
    initABN(a0, r0, c0, h);
    initABN(a1, r1, c1, h);
    initABN(a2, r2i, c2, h);
    initABN(a3, r3, c3, h);
    fmaQuad(a0, a1, a2, a3, pack2(s2_0), pack2(s2_1), pack2(s2_2), pack2(s2_3),
            sW1e + h4);
    {
        const float4* ef0 = (const float4*)(efea + (size_t)e0 * EE);
        const float4* ef1 = (const float4*)(efea + (size_t)(e0 + 1) * EE);
        const float4* ef2 = (const float4*)(efea + (size_t)(e0 + 2) * EE);
        const float4* ef3 = (const float4*)(efea + (size_t)(e0 + 3) * EE);
#pragma unroll
        for (int q = 0; q < 2; q++) {
            float4 u0 = ef0[q], u1 = ef1[q], u2 = ef2[q], u3 = ef3[q];
            fmaQuad(a0, a1, a2, a3, pack2(u0.x), pack2(u1.x), pack2(u2.x), pack2(u3.x),
                    sW1e + ((1 + 4 * q + 0) << 6) + h4);
            fmaQuad(a0, a1, a2, a3, pack2(u0.y), pack2(u1.y), pack2(u2.y), pack2(u3.y),
                    sW1e + ((1 + 4 * q + 1) << 6) + h4);
            fmaQuad(a0, a1, a2, a3, pack2(u0.z), pack2(u1.z), pack2(u2.z), pack2(u3.z),
                    sW1e + ((1 + 4 * q + 2) << 6) + h4);
            fmaQuad(a0, a1, a2, a3, pack2(u0.w), pack2(u1.w), pack2(u2.w), pack2(u3.w),
                    sW1e + ((1 + 4 * q + 3) << 6) + h4);
        }
    }
    // silu + stage hid: value index i = 4c+o -> hid index j = 16c+4h+o
    {
        float f0[16], f1[16], f2[16], f3[16];
        siluQuarter(a0, f0);
        siluQuarter(a1, f1);
        siluQuarter(a2, f2);
        siluQuarter(a3, f3);
#pragma unroll
        for (int i = 0; i < 16; i++) {
            int rowj = ((i >> 2) << 4) + (h << 2) + (i & 3);
            stW[rowj * 8 + qd] = make_float4(f0[i], f1[i], f2[i], f3[i]);
        }
    }
    __syncwarp();

    // ---- stage 2: msg = silu(hid @ W2 + b2) ----
    loadQuarterN(a0, sB2, h);
#pragma unroll
    for (int m = 0; m < 8; m++) { a1[m] = a0[m]; a2[m] = a0[m]; a3[m] = a0[m]; }
#pragma unroll
    for (int k = 0; k < HH; k++) {
        float4 s = stW[k * 8 + qd];
        fmaQuad(a0, a1, a2, a3, pack2(s.x), pack2(s.y), pack2(s.z), pack2(s.w),
                sW2p + (k << 6) + h4);
    }
    __syncwarp();
    {
        float m0[16], m1[16], m2[16], m3[16];
        siluQuarter(a0, m0);
        siluQuarter(a1, m1);
        siluQuarter(a2, m2);
        siluQuarter(a3, m3);
        float* am0 = &g_aggmsg[(size_t)r0 * HH];
        float* am1 = &g_aggmsg[(size_t)r1 * HH];
        float* am2 = &g_aggmsg[(size_t)r2i * HH];
        float* am3 = &g_aggmsg[(size_t)r3 * HH];
#pragma unroll
        for (int c = 0; c < 4; c++) {
            const int off = (c << 4) + (h << 2);
            red4(am0 + off, m0[4 * c], m0[4 * c + 1], m0[4 * c + 2], m0[4 * c + 3]);
            red4(am1 + off, m1[4 * c], m1[4 * c + 1], m1[4 * c + 2], m1[4 * c + 3]);
            red4(am2 + off, m2[4 * c], m2[4 * c + 1], m2[4 * c + 2], m2[4 * c + 3]);
            red4(am3 + off, m3[4 * c], m3[4 * c + 1], m3[4 * c + 2], m3[4 * c + 3]);
        }
#pragma unroll
        for (int i = 0; i < 16; i++) {
            int rowj = ((i >> 2) << 4) + (h << 2) + (i & 3);
            stW[rowj * 8 + qd] = make_float4(m0[i], m1[i], m2[i], m3[i]);
        }
    }
    __syncwarp();

    // ---- stage 3: cm = silu(msg @ CW1 + cb1) . CW2 + cb2 ----
    loadQuarterN(a0, sCB1, h);
#pragma unroll
    for (int m = 0; m < 8; m++) { a1[m] = a0[m]; a2[m] = a0[m]; a3[m] = a0[m]; }
#pragma unroll
    for (int k = 0; k < HH; k++) {
        float4 s = stW[k * 8 + qd];
        fmaQuad(a0, a1, a2, a3, pack2(s.x), pack2(s.y), pack2(s.z), pack2(s.w),
                sCW1 + (k << 6) + h4);
    }
    float cm0 = 0.0f, cm1 = 0.0f, cm2 = 0.0f, cm3 = 0.0f;
#pragma unroll
    for (int m = 0; m < 8; m++) {
        const int j = ((m >> 1) << 4) + (h << 2) + ((m & 1) << 1);
        const float wA = sCW2[j], wB = sCW2[j + 1];
        float x, y;
        unpack2(a0[m], x, y); cm0 += silu_f(x) * wA + silu_f(y) * wB;
        unpack2(a1[m], x, y); cm1 += silu_f(x) * wA + silu_f(y) * wB;
        unpack2(a2[m], x, y); cm2 += silu_f(x) * wA + silu_f(y) * wB;
        unpack2(a3[m], x, y); cm3 += silu_f(x) * wA + silu_f(y) * wB;
    }
    cm0 += __shfl_xor_sync(0xffffffffu, cm0, 1);
    cm0 += __shfl_xor_sync(0xffffffffu, cm0, 2);
    cm1 += __shfl_xor_sync(0xffffffffu, cm1, 1);
    cm1 += __shfl_xor_sync(0xffffffffu, cm1, 2);
    cm2 += __shfl_xor_sync(0xffffffffu, cm2, 1);
    cm2 += __shfl_xor_sync(0xffffffffu, cm2, 2);
    cm3 += __shfl_xor_sync(0xffffffffu, cm3, 1);
    cm3 += __shfl_xor_sync(0xffffffffu, cm3, 2);
    const float cb2v = sCB2[0];
    float cm; int re;
    if (h == 0)      { cm = cm0 + cb2v; re = r0; }
    else if (h == 1) { cm = cm1 + cb2v; re = r1; }
    else if (h == 2) { cm = cm2 + cb2v; re = r2i; }
    else             { cm = cm3 + cb2v; re = r3; }
    red4(&g_aggf[(size_t)re * 4], sx * cm, sy * cm, sz * cm, 0.0f);
}

// ---------------- node kernel: QUAD-split, natural layout ----------------
#define NODE_SMEM_FLOATS (2 * HH * HH + HH * HH + 2 * HH)
__global__ __launch_bounds__(128, 3) void k_node(
    const float* __restrict__ h_in, float* __restrict__ h_out,
    const float* __restrict__ NW1, const float* __restrict__ NB1,
    const float* __restrict__ NW2, const float* __restrict__ NB2,
    float* __restrict__ out_x, float* __restrict__ out_h, int writeOut) {
    extern __shared__ float sm[];
    float* sW1 = sm;                  // [128][64] natural
    float* sW2 = sW1 + 2 * HH * HH;   // [64][64] natural
    float* sB1 = sW2 + HH * HH;
    float* sB2 = sB1 + HH;
    const int t = threadIdx.x;
    for (int i = t; i < 2 * HH * HH; i += 128) sW1[i] = NW1[i];
    for (int i = t; i < HH * HH; i += 128) sW2[i] = NW2[i];
    for (int i = t; i < HH; i += 128) { sB1[i] = NB1[i]; sB2[i] = NB2[i]; }
    __syncthreads();

    const int wid = t >> 5, lane = t & 31;
    const int h = lane & 3, qd = lane >> 2, h4 = h << 2;
    int n0 = blockIdx.x * 128 + (wid << 5) + (qd << 2);
    if (n0 + 3 >= NN) n0 = NN - 4;

    u64 a0[8], a1[8], a2[8], a3[8];
    loadQuarterN(a0, sB1, h);
#pragma unroll
    for (int m = 0; m < 8; m++) { a1[m] = a0[m]; a2[m] = a0[m]; a3[m] = a0[m]; }
    {
        const float4* p0 = (const float4*)(h_in + (size_t)n0 * HH);
        const float4* p1 = (const float4*)(h_in + (size_t)(n0 + 1) * HH);
        const float4* p2 = (const float4*)(h_in + (size_t)(n0 + 2) * HH);
        const float4* p3 = (const float4*)(h_in + (size_t)(n0 + 3) * HH);
#pragma unroll
        for (int q = 0; q < 16; q++) {
            float4 u0 = p0[q], u1 = p1[q], u2 = p2[q], u3 = p3[q];
            fmaQuad(a0, a1, a2, a3, pack2(u0.x), pack2(u1.x), pack2(u2.x), pack2(u3.x),
                    sW1 + ((4 * q + 0) << 6) + h4);
            fmaQuad(a0, a1, a2, a3, pack2(u0.y), pack2(u1.y), pack2(u2.y), pack2(u3.y),
                    sW1 + ((4 * q + 1) << 6) + h4);
            fmaQuad(a0, a1, a2, a3, pack2(u0.z), pack2(u1.z), pack2(u2.z), pack2(u3.z),
                    sW1 + ((4 * q + 2) << 6) + h4);
            fmaQuad(a0, a1, a2, a3, pack2(u0.w), pack2(u1.w), pack2(u2.w), pack2(u3.w),
                    sW1 + ((4 * q + 3) << 6) + h4);
        }
        const float4* m0 = (const float4*)(g_aggmsg + (size_t)n0 * HH);
        const float4* m1 = (const float4*)(g_aggmsg + (size_t)(n0 + 1) * HH);
        const float4* m2 = (const float4*)(g_aggmsg + (size_t)(n0 + 2) * HH);
        const float4* m3 = (const float4*)(g_aggmsg + (size_t)(n0 + 3) * HH);
#pragma unroll
        for (int q = 0; q < 16; q++) {
            float4 u0 = m0[q], u1 = m1[q], u2 = m2[q], u3 = m3[q];
            fmaQuad(a0, a1, a2, a3, pack2(u0.x), pack2(u1.x), pack2(u2.x), pack2(u3.x),
                    sW1 + ((HH + 4 * q + 0) << 6) + h4);
            fmaQuad(a0, a1, a2, a3, pack2(u0.y), pack2(u1.y), pack2(u2.y), pack2(u3.y),
                    sW1 + ((HH + 4 * q + 1) << 6) + h4);
            fmaQuad(a0, a1, a2, a3, pack2(u0.z), pack2(u1.z), pack2(u2.z), pack2(u3.z),
                    sW1 + ((HH + 4 * q + 2) << 6) + h4);
            fmaQuad(a0, a1, a2, a3, pack2(u0.w), pack2(u1.w), pack2(u2.w), pack2(u3.w),
                    sW1 + ((HH + 4 * q + 3) << 6) + h4);
        }
    }
    float hid0[16], hid1[16], hid2[16], hid3[16];
    siluQuarter(a0, hid0);
    siluQuarter(a1, hid1);
    siluQuarter(a2, hid2);
    siluQuarter(a3, hid3);

    loadQuarterN(a0, sB2, h);
#pragma unroll
    for (int m = 0; m < 8; m++) { a1[m] = a0[m]; a2[m] = a0[m]; a3[m] = a0[m]; }
#pragma unroll
    for (int k = 0; k < HH; k++) {
        const int src = (lane & ~3) | ((k >> 2) & 3);
        const int mi = ((k >> 4) << 2) + (k & 3);
        float s0 = __shfl_sync(0xffffffffu, hid0[mi], src);
        float s1 = __shfl_sync(0xffffffffu, hid1[mi], src);
        float s2 = __shfl_sync(0xffffffffu, hid2[mi], src);
        float s3 = __shfl_sync(0xffffffffu, hid3[mi], src);
        fmaQuad(a0, a1, a2, a3, pack2(s0), pack2(s1), pack2(s2), pack2(s3),
                sW2 + (k << 6) + h4);
    }

    {
        float* base = writeOut ? out_h : h_out;
        const u64* as[4] = {a0, a1, a2, a3};
#pragma unroll
        for (int i = 0; i < 4; i++) {
            float* dst = base + (size_t)(n0 + i) * HH + h4;
#pragma unroll
            for (int c = 0; c < 4; c++) {
                float x0, y0, x1, y1;
                unpack2(as[i][2 * c], x0, y0);
                unpack2(as[i][2 * c + 1], x1, y1);
                *(float4*)(dst + (c << 4)) = make_float4(x0, y0, x1, y1);
            }
        }
    }
    // coord update: lane h handles node n0+h (packed layout)
    {
        const int n = n0 + h;
        float cnt = g_cnt[n];
        float inv = 1.0f / fmaxf(cnt, 1.0f);
        float4 xp = g_x4[n];
        float4 af = *(float4*)&g_aggf[(size_t)n * 4];
        float tx = fminf(fmaxf(af.x * inv, -100.0f), 100.0f);
        float ty = fminf(fmaxf(af.y * inv, -100.0f), 100.0f);
        float tz = fminf(fmaxf(af.z * inv, -100.0f), 100.0f);
        xp.x += tx; xp.y += ty; xp.z += tz;
        g_x4[n] = xp;
        if (writeOut) {
            out_x[n * 3 + 0] = xp.x;
            out_x[n * 3 + 1] = xp.y;
            out_x[n * 3 + 2] = xp.z;
        }
    }
}

// ---------------- launch ----------------
extern "C" void kernel_launch(void* const* d_in, const int* in_sizes, int n_in,
                              void* d_out, int out_size) {
    const float* x    = (const float*)d_in[0];
    const float* h    = (const float*)d_in[1];
    const int*   row  = (const int*)d_in[2];
    const int*   col  = (const int*)d_in[3];
    const float* efea = (const float*)d_in[4];
    const float* embW = (const float*)d_in[5];
    const float* embB = (const float*)d_in[6];
    const float* eW1  = (const float*)d_in[7];
    const float* eB1  = (const float*)d_in[8];
    const float* eW2  = (const float*)d_in[9];
    const float* eB2  = (const float*)d_in[10];
    const float* cW1  = (const float*)d_in[11];
    const float* cB1  = (const float*)d_in[12];
    const float* cW2  = (const float*)d_in[13];
    const float* cB2  = (const float*)d_in[14];
    const float* nW1  = (const float*)d_in[15];
    const float* nB1  = (const float*)d_in[16];
    const float* nW2  = (const float*)d_in[17];
    const float* nB2  = (const float*)d_in[18];
    float* out = (float*)d_out;

    void *p_h0, *p_h1, *p_am, *p_af, *p_cnt;
    cudaGetSymbolAddress(&p_h0, g_h0);
    cudaGetSymbolAddress(&p_h1, g_h1);
    cudaGetSymbolAddress(&p_am, g_aggmsg);
    cudaGetSymbolAddress(&p_af, g_aggf);
    cudaGetSymbolAddress(&p_cnt, g_cnt);

    const int edge_smem   = EDGE_SMEM_FLOATS * sizeof(float);
    const int node_smem   = NODE_SMEM_FLOATS * sizeof(float);
    const int pre_smem    = PRE_SMEM_FLOATS * sizeof(float);
    const int preemb_smem = PREEMB_SMEM_FLOATS * sizeof(float);
    cudaFuncSetAttribute(k_edge, cudaFuncAttributeMaxDynamicSharedMemorySize, edge_smem);
    cudaFuncSetAttribute(k_node, cudaFuncAttributeMaxDynamicSharedMemorySize, node_smem);
    cudaFuncSetAttribute(k_pre,  cudaFuncAttributeMaxDynamicSharedMemorySize, pre_smem);
    cudaFuncSetAttribute(k_embed_pre, cudaFuncAttributeMaxDynamicSharedMemorySize, preemb_smem);

    cudaMemsetAsync(p_cnt, 0, NN * sizeof(float), 0);
    k_packx<<<(NN + 255) / 256, 256>>>(x);
    k_cnt<<<(MM + 255) / 256, 256>>>(row);
    k_embed_pre<<<(NN + 127) / 128, 128, preemb_smem>>>(h, embW, embB, eW1, eB1);

    float* hbuf[2] = {(float*)p_h0, (float*)p_h1};
    float* out_x = out;
    float* out_h = out + (size_t)NN * 3;
    const int node_grid = (NN + 127) / 128;   // 391

    for (int i = 0; i < LL; i++) {
        cudaMemsetAsync(p_am, 0, (size_t)NN * HH * sizeof(float), 0);
        cudaMemsetAsync(p_af, 0, (size_t)NN * 4 * sizeof(float), 0);
        if (i > 0)
            k_pre<<<(NN + 127) / 128, 128, pre_smem>>>(
                hbuf[i & 1], eW1 + (size_t)i * DIN * HH, eB1 + (size_t)i * HH);
        k_edge<<<MM / 256, 256, edge_smem>>>(
            row, col, efea,
            eW1 + (size_t)i * DIN * HH,
            eW2 + (size_t)i * HH * HH,  eB2 + (size_t)i * HH,
            cW1 + (size_t)i * HH * HH,  cB1 + (size_t)i * HH,
            cW2 + (size_t)i * HH,       cB2 + (size_t)i * 1);
        k_node<<<node_grid, 128, node_smem>>>(
            hbuf[i & 1], hbuf[(i + 1) & 1],
            nW1 + (size_t)i * 2 * HH * HH, nB1 + (size_t)i * HH,
            nW2 + (size_t)i * HH * HH,     nB2 + (size_t)i * HH,
            out_x, out_h, (i == LL - 1) ? 1 : 0);
    }
    (void)in_sizes; (void)n_in; (void)out_size;
}